// round 2
// baseline (speedup 1.0000x reference)
#include <cuda_runtime.h>
#include <cstddef>

// Problem constants
#define M_TOK   8192     // M*B token rows
#define D_MODEL 1024
#define FF_DIM  4096
#define NHEAD   16
#define DHEAD   64
#define SEQ     1024
#define BATCH   8

// ---------------- scratch (static device memory; no allocations allowed) ----------------
// floats:
//  xn     8388608
//  v      8388608
//  pool   8388608
//  x2     8388608
//  h      33554432
//  qs     131072
//  ks     131072
//  wqs    16384
//  wks    16384
//  bqs    16
//  bks    16
static const size_t OFF_XN   = 0;
static const size_t OFF_V    = 8388608;
static const size_t OFF_POOL = 16777216;
static const size_t OFF_X2   = 25165824;
static const size_t OFF_H    = 33554432;
static const size_t OFF_QS   = 67108864;
static const size_t OFF_KS   = 67239936;
static const size_t OFF_WQS  = 67371008;
static const size_t OFF_WKS  = 67387392;
static const size_t OFF_BQS  = 67403776;
static const size_t OFF_BKS  = 67403792;
static const size_t SCRATCH_FLOATS = 67403808;

__device__ float g_scratch[SCRATCH_FLOATS];

// ---------------- LayerNorm: one block per row (D=1024, 256 threads x float4) ----------------
__global__ void __launch_bounds__(256)
ln_kernel(const float* __restrict__ x, const float* __restrict__ g,
          const float* __restrict__ bta, float* __restrict__ y)
{
    const int row = blockIdx.x;
    const int tx  = threadIdx.x;
    const float4 v = ((const float4*)(x + (size_t)row * D_MODEL))[tx];

    float s  = v.x + v.y + v.z + v.w;
    float sq = v.x * v.x + v.y * v.y + v.z * v.z + v.w * v.w;
    #pragma unroll
    for (int o = 16; o; o >>= 1) {
        s  += __shfl_xor_sync(0xffffffffu, s,  o);
        sq += __shfl_xor_sync(0xffffffffu, sq, o);
    }
    __shared__ float ss[8], ssq[8];
    const int w = tx >> 5, l = tx & 31;
    if (l == 0) { ss[w] = s; ssq[w] = sq; }
    __syncthreads();
    s = 0.f; sq = 0.f;
    #pragma unroll
    for (int i = 0; i < 8; i++) { s += ss[i]; sq += ssq[i]; }

    const float mean = s * (1.f / D_MODEL);
    const float var  = sq * (1.f / D_MODEL) - mean * mean;
    const float rstd = rsqrtf(var + 1e-5f);

    const float4 gv = ((const float4*)g)[tx];
    const float4 bv = ((const float4*)bta)[tx];
    float4 o4;
    o4.x = (v.x - mean) * rstd * gv.x + bv.x;
    o4.y = (v.y - mean) * rstd * gv.y + bv.y;
    o4.z = (v.z - mean) * rstd * gv.z + bv.z;
    o4.w = (v.w - mean) * rstd * gv.w + bv.w;
    ((float4*)(y + (size_t)row * D_MODEL))[tx] = o4;
}

// ---------------- head-sum of wq/wk columns (rank-1 attention folding) ----------------
__global__ void headsum_kernel(const float* __restrict__ wq, const float* __restrict__ bq,
                               const float* __restrict__ wk, const float* __restrict__ bk,
                               float* __restrict__ wqs, float* __restrict__ wks,
                               float* __restrict__ bqs, float* __restrict__ bks)
{
    const int idx = blockIdx.x * blockDim.x + threadIdx.x;
    if (idx < D_MODEL * NHEAD) {
        const int d = idx >> 4, h = idx & 15;
        const float* pq = wq + (size_t)d * D_MODEL + h * DHEAD;
        const float* pk = wk + (size_t)d * D_MODEL + h * DHEAD;
        float sq = 0.f, sk = 0.f;
        #pragma unroll 8
        for (int i = 0; i < DHEAD; i++) { sq += pq[i]; sk += pk[i]; }
        wqs[idx] = sq; wks[idx] = sk;
    }
    if (idx < NHEAD) {
        float sq = 0.f, sk = 0.f;
        for (int i = 0; i < DHEAD; i++) {
            sq += bq[idx * DHEAD + i];
            sk += bk[idx * DHEAD + i];
        }
        bqs[idx] = sq; bks[idx] = sk;
    }
}

// ---------------- skinny GEMM: qs/ks = xn @ wqs/wks + b  (one warp per token row) ----------------
__global__ void __launch_bounds__(256)
qsks_kernel(const float* __restrict__ xn,
            const float* __restrict__ wqs, const float* __restrict__ bqs,
            const float* __restrict__ wks, const float* __restrict__ bks,
            float* __restrict__ qs, float* __restrict__ ks)
{
    const int gw   = (blockIdx.x * blockDim.x + threadIdx.x) >> 5;
    const int lane = threadIdx.x & 31;
    if (gw >= M_TOK) return;

    const float* xr = xn + (size_t)gw * D_MODEL;
    float aq[NHEAD], ak[NHEAD];
    #pragma unroll
    for (int hh = 0; hh < NHEAD; hh++) { aq[hh] = 0.f; ak[hh] = 0.f; }

    for (int d = lane; d < D_MODEL; d += 32) {
        const float xv = xr[d];
        const float* wq = wqs + d * NHEAD;
        const float* wk = wks + d * NHEAD;
        #pragma unroll
        for (int hh = 0; hh < NHEAD; hh++) {
            aq[hh] = fmaf(xv, wq[hh], aq[hh]);
            ak[hh] = fmaf(xv, wk[hh], ak[hh]);
        }
    }
    #pragma unroll
    for (int hh = 0; hh < NHEAD; hh++) {
        #pragma unroll
        for (int o = 16; o; o >>= 1) {
            aq[hh] += __shfl_xor_sync(0xffffffffu, aq[hh], o);
            ak[hh] += __shfl_xor_sync(0xffffffffu, ak[hh], o);
        }
    }
    if (lane == 0) {
        #pragma unroll
        for (int hh = 0; hh < NHEAD; hh++) {
            qs[(size_t)gw * NHEAD + hh] = aq[hh] + bqs[hh];
            ks[(size_t)gw * NHEAD + hh] = ak[hh] + bks[hh];
        }
    }
}

// ---------------- SGEMM 128x128x8, 256 threads, 8x8 per thread ----------------
// C[M_TOK, N] = A[M_TOK, K] @ W[K, N] + bias (+resid) (relu). All dims multiples of 128/8.
template<bool RELU, bool RESID>
__global__ void __launch_bounds__(256)
sgemm_kernel(const float* __restrict__ A, const float* __restrict__ W,
             const float* __restrict__ bias, const float* __restrict__ resid,
             float* __restrict__ C, int N, int K)
{
    __shared__ float As[8][128];
    __shared__ float Ws[8][128];

    const int tx   = threadIdx.x;
    const int brow = blockIdx.y << 7;
    const int bcol = blockIdx.x << 7;
    const int tm   = (tx >> 4) << 3;
    const int tn   = (tx & 15) << 3;

    float acc[8][8];
    #pragma unroll
    for (int i = 0; i < 8; i++)
        #pragma unroll
        for (int j = 0; j < 8; j++) acc[i][j] = 0.f;

    const int aRow = tx >> 1;
    const int aCol = (tx & 1) << 2;
    const int wRow = tx >> 5;
    const int wCol = (tx & 31) << 2;

    const float* Ap = A + (size_t)(brow + aRow) * K + aCol;
    const float* Wp = W + (size_t)wRow * N + bcol + wCol;

    for (int k0 = 0; k0 < K; k0 += 8) {
        const float4 a4 = *(const float4*)(Ap + k0);
        As[aCol + 0][aRow] = a4.x;
        As[aCol + 1][aRow] = a4.y;
        As[aCol + 2][aRow] = a4.z;
        As[aCol + 3][aRow] = a4.w;
        *(float4*)&Ws[wRow][wCol] = *(const float4*)(Wp + (size_t)k0 * N);
        __syncthreads();

        #pragma unroll
        for (int kk = 0; kk < 8; kk++) {
            float ra[8], rb[8];
            #pragma unroll
            for (int i = 0; i < 8; i++) ra[i] = As[kk][tm + i];
            #pragma unroll
            for (int j = 0; j < 8; j++) rb[j] = Ws[kk][tn + j];
            #pragma unroll
            for (int i = 0; i < 8; i++)
                #pragma unroll
                for (int j = 0; j < 8; j++)
                    acc[i][j] = fmaf(ra[i], rb[j], acc[i][j]);
        }
        __syncthreads();
    }

    #pragma unroll
    for (int i = 0; i < 8; i++) {
        const size_t r = (size_t)(brow + tm + i);
        #pragma unroll
        for (int j = 0; j < 8; j += 4) {
            const int c = bcol + tn + j;
            const float4 bv = *(const float4*)(bias + c);
            float4 o;
            o.x = acc[i][j + 0] + bv.x;
            o.y = acc[i][j + 1] + bv.y;
            o.z = acc[i][j + 2] + bv.z;
            o.w = acc[i][j + 3] + bv.w;
            if (RESID) {
                const float4 rv = *(const float4*)(resid + r * N + c);
                o.x += rv.x; o.y += rv.y; o.z += rv.z; o.w += rv.w;
            }
            if (RELU) {
                o.x = fmaxf(o.x, 0.f); o.y = fmaxf(o.y, 0.f);
                o.z = fmaxf(o.z, 0.f); o.w = fmaxf(o.w, 0.f);
            }
            *(float4*)(C + r * N + c) = o;
        }
    }
}

// ---------------- attention: rank-1 scores + online softmax + P@V ----------------
// grid: (SEQ/64, BATCH*NHEAD). block 256. Each block: 64 queries of one (b,h).
__global__ void __launch_bounds__(256)
attn_kernel(const float* __restrict__ qs, const float* __restrict__ ks,
            const float* __restrict__ v, const unsigned char* __restrict__ mask,
            float* __restrict__ o)
{
    __shared__ float Vs[64][68];
    __shared__ float Ps[64][68];
    __shared__ float kss[64];
    __shared__ float qss[64];
    __shared__ unsigned char msk[64];

    const int tx = threadIdx.x;
    const int bh = blockIdx.y;
    const int b  = bh >> 4;
    const int h  = bh & 15;
    const int m0 = blockIdx.x << 6;

    const int row = tx >> 2;
    const int qd  = tx & 3;
    const int c0  = qd << 4;

    if (tx < 64)
        qss[tx] = qs[((size_t)(m0 + tx) * BATCH + b) * NHEAD + h];

    float m_run = -1e30f, l_run = 0.f;
    float acc[16];
    #pragma unroll
    for (int j = 0; j < 16; j++) acc[j] = 0.f;

    for (int n0 = 0; n0 < SEQ; n0 += 64) {
        __syncthreads();   // previous Ps/Vs fully consumed
        if (tx < 64) {
            kss[tx] = ks[((size_t)(n0 + tx) * BATCH + b) * NHEAD + h];
            msk[tx] = mask[(size_t)(n0 + tx) * BATCH + b];
        }
        #pragma unroll
        for (int t = 0; t < 4; t++) {
            const int idx = tx + (t << 8);
            const int n   = idx >> 4;
            const int j4  = (idx & 15) << 2;
            *(float4*)&Vs[n][j4] =
                *(const float4*)(v + ((size_t)(n0 + n) * BATCH + b) * D_MODEL + h * DHEAD + j4);
        }
        __syncthreads();

        const float qv = qss[row];
        float s[16];
        float tmax = -1e30f;
        #pragma unroll
        for (int cc = 0; cc < 16; cc++) {
            const float sv = msk[c0 + cc] ? -1000.0f : qv * kss[c0 + cc];
            s[cc] = sv;
            tmax = fmaxf(tmax, sv);
        }
        tmax = fmaxf(tmax, __shfl_xor_sync(0xffffffffu, tmax, 1));
        tmax = fmaxf(tmax, __shfl_xor_sync(0xffffffffu, tmax, 2));
        const float m_new = fmaxf(m_run, tmax);

        float psum = 0.f;
        #pragma unroll
        for (int cc = 0; cc < 16; cc++) {
            const float p = __expf(s[cc] - m_new);
            Ps[row][c0 + cc] = p;
            psum += p;
        }
        psum += __shfl_xor_sync(0xffffffffu, psum, 1);
        psum += __shfl_xor_sync(0xffffffffu, psum, 2);

        const float scale = __expf(m_run - m_new);
        l_run = l_run * scale + psum;
        m_run = m_new;
        #pragma unroll
        for (int j = 0; j < 16; j++) acc[j] *= scale;
        __syncthreads();   // Ps complete

        #pragma unroll 4
        for (int n = 0; n < 64; n++) {
            const float pv = Ps[row][n];
            const float4* vrow = (const float4*)&Vs[n][c0];
            const float4 v0 = vrow[0], v1 = vrow[1], v2 = vrow[2], v3 = vrow[3];
            acc[0]  = fmaf(pv, v0.x, acc[0]);  acc[1]  = fmaf(pv, v0.y, acc[1]);
            acc[2]  = fmaf(pv, v0.z, acc[2]);  acc[3]  = fmaf(pv, v0.w, acc[3]);
            acc[4]  = fmaf(pv, v1.x, acc[4]);  acc[5]  = fmaf(pv, v1.y, acc[5]);
            acc[6]  = fmaf(pv, v1.z, acc[6]);  acc[7]  = fmaf(pv, v1.w, acc[7]);
            acc[8]  = fmaf(pv, v2.x, acc[8]);  acc[9]  = fmaf(pv, v2.y, acc[9]);
            acc[10] = fmaf(pv, v2.z, acc[10]); acc[11] = fmaf(pv, v2.w, acc[11]);
            acc[12] = fmaf(pv, v3.x, acc[12]); acc[13] = fmaf(pv, v3.y, acc[13]);
            acc[14] = fmaf(pv, v3.z, acc[14]); acc[15] = fmaf(pv, v3.w, acc[15]);
        }
    }

    const float inv = 1.f / l_run;
    const size_t r = (size_t)(m0 + row) * BATCH + b;
    #pragma unroll
    for (int j = 0; j < 16; j += 4) {
        float4 ov;
        ov.x = acc[j + 0] * inv; ov.y = acc[j + 1] * inv;
        ov.z = acc[j + 2] * inv; ov.w = acc[j + 3] * inv;
        *(float4*)(o + r * D_MODEL + h * DHEAD + c0 + j) = ov;
    }
}

// ---------------- launcher ----------------
extern "C" void kernel_launch(void* const* d_in, const int* in_sizes, int n_in,
                              void* d_out, int out_size)
{
    const float* x     = (const float*)d_in[0];
    const unsigned char* mask = (const unsigned char*)d_in[1];
    const float* ln1_g = (const float*)d_in[2];
    const float* ln1_b = (const float*)d_in[3];
    const float* wq    = (const float*)d_in[4];
    const float* bq    = (const float*)d_in[5];
    const float* wk    = (const float*)d_in[6];
    const float* bk    = (const float*)d_in[7];
    const float* wv    = (const float*)d_in[8];
    const float* bv    = (const float*)d_in[9];
    const float* wo    = (const float*)d_in[10];
    const float* bo    = (const float*)d_in[11];
    const float* ln2_g = (const float*)d_in[12];
    const float* ln2_b = (const float*)d_in[13];
    const float* w1    = (const float*)d_in[14];
    const float* b1    = (const float*)d_in[15];
    const float* w2    = (const float*)d_in[16];
    const float* b2    = (const float*)d_in[17];
    float* out = (float*)d_out;

    float* scratch = nullptr;
    cudaGetSymbolAddress((void**)&scratch, g_scratch);
    float* xn   = scratch + OFF_XN;
    float* vbuf = scratch + OFF_V;
    float* pool = scratch + OFF_POOL;
    float* x2   = scratch + OFF_X2;
    float* hbuf = scratch + OFF_H;
    float* qsb  = scratch + OFF_QS;
    float* ksb  = scratch + OFF_KS;
    float* wqs  = scratch + OFF_WQS;
    float* wks  = scratch + OFF_WKS;
    float* bqs  = scratch + OFF_BQS;
    float* bks  = scratch + OFF_BKS;

    // 1. xn = LN1(x)
    ln_kernel<<<M_TOK, 256>>>(x, ln1_g, ln1_b, xn);
    // 2. fold head-sums of wq/wk (rank-1 attention)
    headsum_kernel<<<64, 256>>>(wq, bq, wk, bk, wqs, wks, bqs, bks);
    // 3. v = xn @ wv + bv
    sgemm_kernel<false, false><<<dim3(D_MODEL / 128, M_TOK / 128), 256>>>(
        xn, wv, bv, nullptr, vbuf, D_MODEL, D_MODEL);
    // 4. qs/ks = xn @ wqs/wks + b (skinny)
    qsks_kernel<<<M_TOK / 8, 256>>>(xn, wqs, bqs, wks, bks, qsb, ksb);
    // 5. pooled = softmax(qs ⊗ ks, masked) @ v
    attn_kernel<<<dim3(SEQ / 64, BATCH * NHEAD), 256>>>(qsb, ksb, vbuf, mask, pool);
    // 6. x2 = pooled @ wo + bo + x
    sgemm_kernel<false, true><<<dim3(D_MODEL / 128, M_TOK / 128), 256>>>(
        pool, wo, bo, x, x2, D_MODEL, D_MODEL);
    // 7. xn = LN2(x2)
    ln_kernel<<<M_TOK, 256>>>(x2, ln2_g, ln2_b, xn);
    // 8. h = relu(xn @ w1 + b1)
    sgemm_kernel<true, false><<<dim3(FF_DIM / 128, M_TOK / 128), 256>>>(
        xn, w1, b1, nullptr, hbuf, FF_DIM, D_MODEL);
    // 9. out = h @ w2 + b2 + x2
    sgemm_kernel<false, true><<<dim3(D_MODEL / 128, M_TOK / 128), 256>>>(
        hbuf, w2, b2, x2, out, D_MODEL, FF_DIM);
}

// round 3
// speedup vs baseline: 1.6318x; 1.6318x over previous
#include <cuda_runtime.h>
#include <cstddef>

// Problem constants
#define M_TOK   8192     // M*B token rows
#define D_MODEL 1024
#define FF_DIM  4096
#define NHEAD   16
#define DHEAD   64
#define SEQ     1024
#define BATCH   8

typedef unsigned long long ull;

// ---------------- packed f32x2 helpers (B300: FFMA2 doubles fp32 FMA throughput) ----
__device__ __forceinline__ ull pack2(float x, float y) {
    ull r; asm("mov.b64 %0, {%1, %2};" : "=l"(r) : "f"(x), "f"(y)); return r;
}
__device__ __forceinline__ float2 unpack2(ull v) {
    float2 r; asm("mov.b64 {%0, %1}, %2;" : "=f"(r.x), "=f"(r.y) : "l"(v)); return r;
}
__device__ __forceinline__ void fma2(ull& d, ull a, ull b) {
    asm("fma.rn.f32x2 %0, %1, %2, %0;" : "+l"(d) : "l"(a), "l"(b));
}
__device__ __forceinline__ void mul2(ull& d, ull a) {
    asm("mul.rn.f32x2 %0, %0, %1;" : "+l"(d) : "l"(a));
}

// ---------------- scratch (static device memory) ----------------
static const size_t OFF_XN   = 0;
static const size_t OFF_V    = 8388608;
static const size_t OFF_POOL = 16777216;
static const size_t OFF_X2   = 25165824;
static const size_t OFF_H    = 33554432;
static const size_t OFF_QS   = 67108864;
static const size_t OFF_KS   = 67239936;
static const size_t OFF_WQK  = 67371008;   // [1024][32]
static const size_t OFF_BQK  = 67403776;   // [32]
static const size_t SCRATCH_FLOATS = 67403808;

__device__ float g_scratch[SCRATCH_FLOATS];

// ---------------- LayerNorm ----------------
__global__ void __launch_bounds__(256)
ln_kernel(const float* __restrict__ x, const float* __restrict__ g,
          const float* __restrict__ bta, float* __restrict__ y)
{
    const int row = blockIdx.x;
    const int tx  = threadIdx.x;
    const float4 v = ((const float4*)(x + (size_t)row * D_MODEL))[tx];

    float s  = v.x + v.y + v.z + v.w;
    float sq = v.x * v.x + v.y * v.y + v.z * v.z + v.w * v.w;
    #pragma unroll
    for (int o = 16; o; o >>= 1) {
        s  += __shfl_xor_sync(0xffffffffu, s,  o);
        sq += __shfl_xor_sync(0xffffffffu, sq, o);
    }
    __shared__ float ss[8], ssq[8];
    const int w = tx >> 5, l = tx & 31;
    if (l == 0) { ss[w] = s; ssq[w] = sq; }
    __syncthreads();
    s = 0.f; sq = 0.f;
    #pragma unroll
    for (int i = 0; i < 8; i++) { s += ss[i]; sq += ssq[i]; }

    const float mean = s * (1.f / D_MODEL);
    const float var  = sq * (1.f / D_MODEL) - mean * mean;
    const float rstd = rsqrtf(var + 1e-5f);

    const float4 gv = ((const float4*)g)[tx];
    const float4 bv = ((const float4*)bta)[tx];
    float4 o4;
    o4.x = (v.x - mean) * rstd * gv.x + bv.x;
    o4.y = (v.y - mean) * rstd * gv.y + bv.y;
    o4.z = (v.z - mean) * rstd * gv.z + bv.z;
    o4.w = (v.w - mean) * rstd * gv.w + bv.w;
    ((float4*)(y + (size_t)row * D_MODEL))[tx] = o4;
}

// ---------------- head-sum of wq/wk columns into combined [1024][32] ----------------
__global__ void headsum_kernel(const float* __restrict__ wq, const float* __restrict__ bq,
                               const float* __restrict__ wk, const float* __restrict__ bk,
                               float* __restrict__ wqk, float* __restrict__ bqk)
{
    const int idx = blockIdx.x * blockDim.x + threadIdx.x;
    if (idx < D_MODEL * NHEAD) {
        const int d = idx >> 4, h = idx & 15;
        const float* pq = wq + (size_t)d * D_MODEL + h * DHEAD;
        const float* pk = wk + (size_t)d * D_MODEL + h * DHEAD;
        float sq = 0.f, sk = 0.f;
        #pragma unroll 8
        for (int i = 0; i < DHEAD; i++) { sq += pq[i]; sk += pk[i]; }
        wqk[d * 32 + h]      = sq;
        wqk[d * 32 + 16 + h] = sk;
    }
    if (idx < NHEAD) {
        float sq = 0.f, sk = 0.f;
        for (int i = 0; i < DHEAD; i++) {
            sq += bq[idx * DHEAD + i];
            sk += bk[idx * DHEAD + i];
        }
        bqk[idx] = sq; bqk[16 + idx] = sk;
    }
}

// ---------------- tiled skinny GEMM: C[8192,32] = xn @ wqk + bqk → qs|ks --------------
__global__ void __launch_bounds__(256)
qsks_gemm(const float* __restrict__ xn, const float* __restrict__ wqk,
          const float* __restrict__ bqk, float* __restrict__ qs, float* __restrict__ ks)
{
    __shared__ float Asm[32][132];   // [kk][row], stride 132 keeps 16B alignment
    __shared__ float Wsm[32][36];    // [kk][col]

    const int tx   = threadIdx.x;
    const int brow = blockIdx.x << 7;
    const int tm   = (tx >> 3) << 2;   // 4 rows
    const int tn   = (tx & 7) << 2;    // 4 cols

    float acc[4][4];
    #pragma unroll
    for (int i = 0; i < 4; i++)
        #pragma unroll
        for (int j = 0; j < 4; j++) acc[i][j] = 0.f;

    for (int k0 = 0; k0 < D_MODEL; k0 += 32) {
        #pragma unroll
        for (int t = 0; t < 4; t++) {
            const int idx = tx + (t << 8);
            const int r   = idx >> 3;
            const int c4  = (idx & 7) << 2;
            const float4 a4 = *(const float4*)(xn + (size_t)(brow + r) * D_MODEL + k0 + c4);
            Asm[c4 + 0][r] = a4.x; Asm[c4 + 1][r] = a4.y;
            Asm[c4 + 2][r] = a4.z; Asm[c4 + 3][r] = a4.w;
        }
        {
            const int r  = tx >> 3;
            const int c4 = (tx & 7) << 2;
            *(float4*)&Wsm[r][c4] = *(const float4*)(wqk + (size_t)(k0 + r) * 32 + c4);
        }
        __syncthreads();

        #pragma unroll
        for (int kk = 0; kk < 32; kk++) {
            float ra[4], rb[4];
            *(float4*)ra = *(const float4*)&Asm[kk][tm];
            *(float4*)rb = *(const float4*)&Wsm[kk][tn];
            #pragma unroll
            for (int i = 0; i < 4; i++)
                #pragma unroll
                for (int j = 0; j < 4; j++)
                    acc[i][j] = fmaf(ra[i], rb[j], acc[i][j]);
        }
        __syncthreads();
    }

    #pragma unroll
    for (int i = 0; i < 4; i++) {
        const size_t row = (size_t)(brow + tm + i);
        #pragma unroll
        for (int j = 0; j < 4; j++) {
            const int c = tn + j;
            const float v = acc[i][j] + bqk[c];
            if (c < 16) qs[row * NHEAD + c]        = v;
            else        ks[row * NHEAD + (c - 16)] = v;
        }
    }
}

// ---------------- SGEMM 128x128x8, f32x2 FMA, double-buffered smem ----------------
template<bool RELU, bool RESID>
__global__ void __launch_bounds__(256, 2)
sgemm_kernel(const float* __restrict__ A, const float* __restrict__ W,
             const float* __restrict__ bias, const float* __restrict__ resid,
             float* __restrict__ C, int N, int K)
{
    __shared__ float As2[2][8][256];   // duplicated: As2[buf][kk][2*row+{0,1}]
    __shared__ float Ws[2][8][128];

    const int tx   = threadIdx.x;
    const int brow = blockIdx.y << 7;
    const int bcol = blockIdx.x << 7;
    const int tm   = (tx >> 4) << 3;
    const int tn   = (tx & 15) << 3;

    ull acc[8][4];
    #pragma unroll
    for (int i = 0; i < 8; i++)
        #pragma unroll
        for (int j = 0; j < 4; j++) acc[i][j] = 0ULL;

    const int aRow = tx >> 1;
    const int aCol = (tx & 1) << 2;
    const int wRow = tx >> 5;
    const int wCol = (tx & 31) << 2;

    const float* Ap = A + (size_t)(brow + aRow) * K + aCol;
    const float* Wp = W + (size_t)wRow * N + bcol + wCol;

    // stage 0
    {
        const float4 a4 = *(const float4*)Ap;
        const float4 w4 = *(const float4*)Wp;
        *(float2*)&As2[0][aCol + 0][2 * aRow] = make_float2(a4.x, a4.x);
        *(float2*)&As2[0][aCol + 1][2 * aRow] = make_float2(a4.y, a4.y);
        *(float2*)&As2[0][aCol + 2][2 * aRow] = make_float2(a4.z, a4.z);
        *(float2*)&As2[0][aCol + 3][2 * aRow] = make_float2(a4.w, a4.w);
        *(float4*)&Ws[0][wRow][wCol] = w4;
    }
    __syncthreads();

    int buf = 0;
    for (int k0 = 0; k0 < K; k0 += 8) {
        const bool nxt = (k0 + 8) < K;
        float4 a4n, w4n;
        if (nxt) {
            a4n = *(const float4*)(Ap + k0 + 8);
            w4n = *(const float4*)(Wp + (size_t)(k0 + 8) * N);
        }

        #pragma unroll
        for (int kk = 0; kk < 8; kk++) {
            const ulonglong2* ar = (const ulonglong2*)&As2[buf][kk][2 * tm];
            const ulonglong2 a0 = ar[0], a1 = ar[1], a2 = ar[2], a3 = ar[3];
            const ulonglong2* br = (const ulonglong2*)&Ws[buf][kk][tn];
            const ulonglong2 b0 = br[0], b1 = br[1];
            const ull ra[8] = {a0.x, a0.y, a1.x, a1.y, a2.x, a2.y, a3.x, a3.y};
            const ull rb[4] = {b0.x, b0.y, b1.x, b1.y};
            #pragma unroll
            for (int i = 0; i < 8; i++)
                #pragma unroll
                for (int j = 0; j < 4; j++)
                    fma2(acc[i][j], ra[i], rb[j]);
        }

        if (nxt) {
            const int nb = buf ^ 1;
            *(float2*)&As2[nb][aCol + 0][2 * aRow] = make_float2(a4n.x, a4n.x);
            *(float2*)&As2[nb][aCol + 1][2 * aRow] = make_float2(a4n.y, a4n.y);
            *(float2*)&As2[nb][aCol + 2][2 * aRow] = make_float2(a4n.z, a4n.z);
            *(float2*)&As2[nb][aCol + 3][2 * aRow] = make_float2(a4n.w, a4n.w);
            *(float4*)&Ws[nb][wRow][wCol] = w4n;
        }
        __syncthreads();
        buf ^= 1;
    }

    #pragma unroll
    for (int i = 0; i < 8; i++) {
        const size_t r  = (size_t)(brow + tm + i);
        const int   cb  = bcol + tn;
        const float2 p0 = unpack2(acc[i][0]);
        const float2 p1 = unpack2(acc[i][1]);
        const float2 p2 = unpack2(acc[i][2]);
        const float2 p3 = unpack2(acc[i][3]);
        const float4 bv0 = *(const float4*)(bias + cb);
        const float4 bv1 = *(const float4*)(bias + cb + 4);
        float4 o0, o1;
        o0.x = p0.x + bv0.x; o0.y = p0.y + bv0.y; o0.z = p1.x + bv0.z; o0.w = p1.y + bv0.w;
        o1.x = p2.x + bv1.x; o1.y = p2.y + bv1.y; o1.z = p3.x + bv1.z; o1.w = p3.y + bv1.w;
        if (RESID) {
            const float4 r0 = *(const float4*)(resid + r * N + cb);
            const float4 r1 = *(const float4*)(resid + r * N + cb + 4);
            o0.x += r0.x; o0.y += r0.y; o0.z += r0.z; o0.w += r0.w;
            o1.x += r1.x; o1.y += r1.y; o1.z += r1.z; o1.w += r1.w;
        }
        if (RELU) {
            o0.x = fmaxf(o0.x, 0.f); o0.y = fmaxf(o0.y, 0.f);
            o0.z = fmaxf(o0.z, 0.f); o0.w = fmaxf(o0.w, 0.f);
            o1.x = fmaxf(o1.x, 0.f); o1.y = fmaxf(o1.y, 0.f);
            o1.z = fmaxf(o1.z, 0.f); o1.w = fmaxf(o1.w, 0.f);
        }
        *(float4*)(C + r * N + cb)     = o0;
        *(float4*)(C + r * N + cb + 4) = o1;
    }
}

// ---------------- attention: rank-1 scores + online softmax + P@V (f32x2) ------------
__global__ void __launch_bounds__(256)
attn_kernel(const float* __restrict__ qs, const float* __restrict__ ks,
            const float* __restrict__ v, const unsigned char* __restrict__ mask,
            float* __restrict__ o)
{
    __shared__ float Vs[64][68];
    __shared__ float Ps[64][68];
    __shared__ float kss[64];
    __shared__ float qss[64];
    __shared__ unsigned char msk[64];

    const int tx = threadIdx.x;
    const int bh = blockIdx.y;
    const int b  = bh >> 4;
    const int h  = bh & 15;
    const int m0 = blockIdx.x << 6;

    const int row = tx >> 2;
    const int qd  = tx & 3;
    const int c0  = qd << 4;

    if (tx < 64)
        qss[tx] = qs[((size_t)(m0 + tx) * BATCH + b) * NHEAD + h];

    float m_run = -1e30f, l_run = 0.f;
    ull acc[8];
    #pragma unroll
    for (int j = 0; j < 8; j++) acc[j] = 0ULL;

    for (int n0 = 0; n0 < SEQ; n0 += 64) {
        __syncthreads();
        if (tx < 64) {
            kss[tx] = ks[((size_t)(n0 + tx) * BATCH + b) * NHEAD + h];
            msk[tx] = mask[(size_t)(n0 + tx) * BATCH + b];
        }
        #pragma unroll
        for (int t = 0; t < 4; t++) {
            const int idx = tx + (t << 8);
            const int n   = idx >> 4;
            const int j4  = (idx & 15) << 2;
            *(float4*)&Vs[n][j4] =
                *(const float4*)(v + ((size_t)(n0 + n) * BATCH + b) * D_MODEL + h * DHEAD + j4);
        }
        __syncthreads();

        const float qv = qss[row];
        float s[16];
        float tmax = -1e30f;
        #pragma unroll
        for (int cc = 0; cc < 16; cc++) {
            const float sv = msk[c0 + cc] ? -1000.0f : qv * kss[c0 + cc];
            s[cc] = sv;
            tmax = fmaxf(tmax, sv);
        }
        tmax = fmaxf(tmax, __shfl_xor_sync(0xffffffffu, tmax, 1));
        tmax = fmaxf(tmax, __shfl_xor_sync(0xffffffffu, tmax, 2));
        const float m_new = fmaxf(m_run, tmax);

        float psum = 0.f;
        #pragma unroll
        for (int cc = 0; cc < 16; cc++) {
            const float p = __expf(s[cc] - m_new);
            Ps[row][c0 + cc] = p;
            psum += p;
        }
        psum += __shfl_xor_sync(0xffffffffu, psum, 1);
        psum += __shfl_xor_sync(0xffffffffu, psum, 2);

        const float scale = __expf(m_run - m_new);
        l_run = l_run * scale + psum;
        m_run = m_new;
        const ull sc2 = pack2(scale, scale);
        #pragma unroll
        for (int j = 0; j < 8; j++) mul2(acc[j], sc2);
        __syncthreads();

        #pragma unroll 4
        for (int n = 0; n < 64; n++) {
            const float pv = Ps[row][n];
            const ull pd = pack2(pv, pv);
            const ulonglong2 v01 = *(const ulonglong2*)&Vs[n][c0];
            const ulonglong2 v23 = *(const ulonglong2*)&Vs[n][c0 + 4];
            const ulonglong2 v45 = *(const ulonglong2*)&Vs[n][c0 + 8];
            const ulonglong2 v67 = *(const ulonglong2*)&Vs[n][c0 + 12];
            fma2(acc[0], pd, v01.x); fma2(acc[1], pd, v01.y);
            fma2(acc[2], pd, v23.x); fma2(acc[3], pd, v23.y);
            fma2(acc[4], pd, v45.x); fma2(acc[5], pd, v45.y);
            fma2(acc[6], pd, v67.x); fma2(acc[7], pd, v67.y);
        }
    }

    const float inv = 1.f / l_run;
    const size_t r = (size_t)(m0 + row) * BATCH + b;
    #pragma unroll
    for (int j = 0; j < 4; j++) {
        const float2 pa = unpack2(acc[2 * j]);
        const float2 pb = unpack2(acc[2 * j + 1]);
        float4 ov;
        ov.x = pa.x * inv; ov.y = pa.y * inv;
        ov.z = pb.x * inv; ov.w = pb.y * inv;
        *(float4*)(o + r * D_MODEL + h * DHEAD + c0 + (j << 2)) = ov;
    }
}

// ---------------- launcher ----------------
extern "C" void kernel_launch(void* const* d_in, const int* in_sizes, int n_in,
                              void* d_out, int out_size)
{
    const float* x     = (const float*)d_in[0];
    const unsigned char* mask = (const unsigned char*)d_in[1];
    const float* ln1_g = (const float*)d_in[2];
    const float* ln1_b = (const float*)d_in[3];
    const float* wq    = (const float*)d_in[4];
    const float* bq    = (const float*)d_in[5];
    const float* wk    = (const float*)d_in[6];
    const float* bk    = (const float*)d_in[7];
    const float* wv    = (const float*)d_in[8];
    const float* bv    = (const float*)d_in[9];
    const float* wo    = (const float*)d_in[10];
    const float* bo    = (const float*)d_in[11];
    const float* ln2_g = (const float*)d_in[12];
    const float* ln2_b = (const float*)d_in[13];
    const float* w1    = (const float*)d_in[14];
    const float* b1    = (const float*)d_in[15];
    const float* w2    = (const float*)d_in[16];
    const float* b2    = (const float*)d_in[17];
    float* out = (float*)d_out;

    float* scratch = nullptr;
    cudaGetSymbolAddress((void**)&scratch, g_scratch);
    float* xn   = scratch + OFF_XN;
    float* vbuf = scratch + OFF_V;
    float* pool = scratch + OFF_POOL;
    float* x2   = scratch + OFF_X2;
    float* hbuf = scratch + OFF_H;
    float* qsb  = scratch + OFF_QS;
    float* ksb  = scratch + OFF_KS;
    float* wqk  = scratch + OFF_WQK;
    float* bqk  = scratch + OFF_BQK;

    // 1. xn = LN1(x)
    ln_kernel<<<M_TOK, 256>>>(x, ln1_g, ln1_b, xn);
    // 2. fold head-sums of wq/wk (rank-1 attention)
    headsum_kernel<<<64, 256>>>(wq, bq, wk, bk, wqk, bqk);
    // 3. v = xn @ wv + bv
    sgemm_kernel<false, false><<<dim3(D_MODEL / 128, M_TOK / 128), 256>>>(
        xn, wv, bv, nullptr, vbuf, D_MODEL, D_MODEL);
    // 4. qs/ks = xn @ wqk + bqk (tiled skinny GEMM)
    qsks_gemm<<<M_TOK / 128, 256>>>(xn, wqk, bqk, qsb, ksb);
    // 5. pooled = softmax(qs ⊗ ks, masked) @ v
    attn_kernel<<<dim3(SEQ / 64, BATCH * NHEAD), 256>>>(qsb, ksb, vbuf, mask, pool);
    // 6. x2 = pooled @ wo + bo + x
    sgemm_kernel<false, true><<<dim3(D_MODEL / 128, M_TOK / 128), 256>>>(
        pool, wo, bo, x, x2, D_MODEL, D_MODEL);
    // 7. xn = LN2(x2)
    ln_kernel<<<M_TOK, 256>>>(x2, ln2_g, ln2_b, xn);
    // 8. h = relu(xn @ w1 + b1)
    sgemm_kernel<true, false><<<dim3(FF_DIM / 128, M_TOK / 128), 256>>>(
        xn, w1, b1, nullptr, hbuf, FF_DIM, D_MODEL);
    // 9. out = h @ w2 + b2 + x2
    sgemm_kernel<false, true><<<dim3(D_MODEL / 128, M_TOK / 128), 256>>>(
        hbuf, w2, b2, x2, out, D_MODEL, FF_DIM);
}

// round 5
// speedup vs baseline: 2.4312x; 1.4899x over previous
#include <cuda_runtime.h>
#include <cstddef>
#include <cstdint>

// Problem constants
#define M_TOK   8192     // M*B token rows
#define D_MODEL 1024
#define FF_DIM  4096
#define NHEAD   16
#define DHEAD   64
#define SEQ     1024
#define BATCH   8

// tcgen05 is arch-SPECIFIC (sm_103a). nvcc also runs a generic compute_103 PTX
// pass where these instructions don't exist — compile a stub there. The GPU
// loads the sm_103a cubin, so the stub is never executed.
#if defined(__CUDA_ARCH__) && (defined(__CUDA_ARCH_FEAT_SM103_ALL) || defined(__CUDA_ARCH_SPECIFIC__))
#define HAS_TCGEN05 1
#else
#define HAS_TCGEN05 0
#endif

typedef unsigned long long ull;

// ---------------- packed f32x2 helpers (attention PV) ----------------
__device__ __forceinline__ ull pack2(float x, float y) {
    ull r; asm("mov.b64 %0, {%1, %2};" : "=l"(r) : "f"(x), "f"(y)); return r;
}
__device__ __forceinline__ float2 unpack2(ull v) {
    float2 r; asm("mov.b64 {%0, %1}, %2;" : "=f"(r.x), "=f"(r.y) : "l"(v)); return r;
}
__device__ __forceinline__ void fma2(ull& d, ull a, ull b) {
    asm("fma.rn.f32x2 %0, %1, %2, %0;" : "+l"(d) : "l"(a), "l"(b));
}
__device__ __forceinline__ void mul2(ull& d, ull a) {
    asm("mul.rn.f32x2 %0, %0, %1;" : "+l"(d) : "l"(a));
}

// ---------------- tcgen05 helpers ----------------
#define SMEM_SWIZZLE_128B(byte_offset) ((byte_offset) ^ (((byte_offset) >> 3) & 0x70))

static constexpr uint64_t SMEM_DESC_BASE_SW128 =
    (uint64_t(2)  << 61) | (uint64_t(1) << 46) | (uint64_t(64) << 32) | (uint64_t(1) << 16);
#define MAKE_SMEM_DESC(base_addr) \
    (SMEM_DESC_BASE_SW128 | ((uint64_t)((base_addr) >> 4) & 0x3FFF))

__device__ __forceinline__ uint32_t smem_to_u32(const void* p) {
    uint32_t a;
    asm("{ .reg .u64 t; cvta.to.shared.u64 t, %1; cvt.u32.u64 %0, t; }" : "=r"(a) : "l"(p));
    return a;
}
__device__ __forceinline__ uint32_t tf32_of(float f) {
    uint32_t r; asm("cvt.rna.tf32.f32 %0, %1;" : "=r"(r) : "f"(f)); return r;
}

#if HAS_TCGEN05
#define TCGEN05_ALLOC(smem_res, nCols) \
    asm volatile("tcgen05.alloc.cta_group::1.sync.aligned.shared::cta.b32 [%0], %1;" \
                 :: "r"((uint32_t)(smem_res)), "r"((uint32_t)(nCols)) : "memory")
#define TCGEN05_DEALLOC(tmem, nCols) \
    asm volatile("tcgen05.dealloc.cta_group::1.sync.aligned.b32 %0, %1;" \
                 :: "r"(tmem), "r"((uint32_t)(nCols)))
#define TCGEN05_RELINQUISH() \
    asm volatile("tcgen05.relinquish_alloc_permit.cta_group::1.sync.aligned;")
#define TCGEN05_WAIT_LD() asm volatile("tcgen05.wait::ld.sync.aligned;" ::: "memory")
#define TC_FENCE_AFTER()  asm volatile("tcgen05.fence::after_thread_sync;" ::: "memory")
#define TC_COMMIT(mbar) \
    asm volatile("tcgen05.commit.cta_group::1.mbarrier::arrive::one.shared::cluster.b64 [%0];" \
                 :: "r"((uint32_t)(mbar)) : "memory")
#endif

#define FENCE_PROXY_ASYNC() asm volatile("fence.proxy.async.shared::cta;" ::: "memory")
#define MBARRIER_INIT(mbar, cnt) \
    asm volatile("mbarrier.init.shared.b64 [%0], %1;" :: "r"((uint32_t)(mbar)), "r"((uint32_t)(cnt)) : "memory")
#define MBAR_WAIT(mbar, ph) \
    asm volatile("{\n\t.reg .pred P;\n\tWL%=:\n\t" \
                 "mbarrier.try_wait.parity.acquire.cta.shared::cta.b64 P, [%0], %1, 0x989680;\n\t" \
                 "@!P bra WL%=;\n\t}" :: "r"((uint32_t)(mbar)), "r"((uint32_t)(ph)) : "memory")

#if HAS_TCGEN05
#define TCGEN05_LD_32X32B_X32(r, tmem_addr) \
    asm volatile( \
        "tcgen05.ld.sync.aligned.32x32b.x32.b32 " \
        "{%0, %1, %2, %3, %4, %5, %6, %7, " \
        " %8, %9, %10, %11, %12, %13, %14, %15, " \
        " %16, %17, %18, %19, %20, %21, %22, %23, " \
        " %24, %25, %26, %27, %28, %29, %30, %31}, [%32];" \
        : "=r"((r)[0]),  "=r"((r)[1]),  "=r"((r)[2]),  "=r"((r)[3]), \
          "=r"((r)[4]),  "=r"((r)[5]),  "=r"((r)[6]),  "=r"((r)[7]), \
          "=r"((r)[8]),  "=r"((r)[9]),  "=r"((r)[10]), "=r"((r)[11]), \
          "=r"((r)[12]), "=r"((r)[13]), "=r"((r)[14]), "=r"((r)[15]), \
          "=r"((r)[16]), "=r"((r)[17]), "=r"((r)[18]), "=r"((r)[19]), \
          "=r"((r)[20]), "=r"((r)[21]), "=r"((r)[22]), "=r"((r)[23]), \
          "=r"((r)[24]), "=r"((r)[25]), "=r"((r)[26]), "=r"((r)[27]), \
          "=r"((r)[28]), "=r"((r)[29]), "=r"((r)[30]), "=r"((r)[31]) \
        : "r"(tmem_addr))

// tf32 SS MMA, cg1. idesc: dfmt F32(1<<4) | a TF32(2<<7) | b TF32(2<<10) | (N/8)<<17 | (M/16)<<24
__device__ __forceinline__ void mma_tf32_ss(uint32_t d_tmem, uint64_t a_desc, uint64_t b_desc,
                                            uint32_t idesc, uint32_t en)
{
    asm volatile(
        "{\n\t"
        ".reg .pred p;\n\t"
        "setp.ne.u32 p, %5, 0;\n\t"
        "tcgen05.mma.cta_group::1.kind::tf32 [%0], %1, %2, %3, {%4, %4, %4, %4}, p;\n\t"
        "}"
        :: "r"(d_tmem), "l"(a_desc), "l"(b_desc), "r"(idesc), "r"(0u), "r"(en)
        : "memory");
}
#endif

// ---------------- scratch (static device memory) ----------------
static const size_t OFF_XN   = 0;
static const size_t OFF_V    = 8388608;
static const size_t OFF_POOL = 16777216;
static const size_t OFF_X2   = 25165824;
static const size_t OFF_H    = 33554432;
static const size_t OFF_QS   = 67108864;
static const size_t OFF_KS   = 67239936;
static const size_t OFF_WQK  = 67371008;   // [1024][32]
static const size_t OFF_BQK  = 67403776;   // [32]
static const size_t OFF_WVT  = 67403808;   // [1024][1024]
static const size_t OFF_WOT  = 68452384;
static const size_t OFF_W1T  = 69500960;   // [4096][1024]
static const size_t OFF_W2T  = 73695264;   // [1024][4096]
static const size_t SCRATCH_FLOATS = 77889568;

__device__ float g_scratch[SCRATCH_FLOATS];

// ---------------- LayerNorm ----------------
__global__ void __launch_bounds__(256)
ln_kernel(const float* __restrict__ x, const float* __restrict__ g,
          const float* __restrict__ bta, float* __restrict__ y)
{
    const int row = blockIdx.x;
    const int tx  = threadIdx.x;
    const float4 v = ((const float4*)(x + (size_t)row * D_MODEL))[tx];

    float s  = v.x + v.y + v.z + v.w;
    float sq = v.x * v.x + v.y * v.y + v.z * v.z + v.w * v.w;
    #pragma unroll
    for (int o = 16; o; o >>= 1) {
        s  += __shfl_xor_sync(0xffffffffu, s,  o);
        sq += __shfl_xor_sync(0xffffffffu, sq, o);
    }
    __shared__ float ss[8], ssq[8];
    const int w = tx >> 5, l = tx & 31;
    if (l == 0) { ss[w] = s; ssq[w] = sq; }
    __syncthreads();
    s = 0.f; sq = 0.f;
    #pragma unroll
    for (int i = 0; i < 8; i++) { s += ss[i]; sq += ssq[i]; }

    const float mean = s * (1.f / D_MODEL);
    const float var  = sq * (1.f / D_MODEL) - mean * mean;
    const float rstd = rsqrtf(var + 1e-5f);

    const float4 gv = ((const float4*)g)[tx];
    const float4 bv = ((const float4*)bta)[tx];
    float4 o4;
    o4.x = (v.x - mean) * rstd * gv.x + bv.x;
    o4.y = (v.y - mean) * rstd * gv.y + bv.y;
    o4.z = (v.z - mean) * rstd * gv.z + bv.z;
    o4.w = (v.w - mean) * rstd * gv.w + bv.w;
    ((float4*)(y + (size_t)row * D_MODEL))[tx] = o4;
}

// ---------------- 32x32 tiled transpose: in[R,C] -> out[C,R] ----------------
__global__ void __launch_bounds__(256)
transpose_kernel(const float* __restrict__ in, float* __restrict__ out, int R, int C)
{
    __shared__ float t[32][33];
    const int r0 = blockIdx.y << 5;
    const int c0 = blockIdx.x << 5;
    const int tx = threadIdx.x & 31;
    const int ty = threadIdx.x >> 5;   // 0..7
    #pragma unroll
    for (int i = 0; i < 4; i++)
        t[ty + (i << 3)][tx] = in[(size_t)(r0 + ty + (i << 3)) * C + c0 + tx];
    __syncthreads();
    #pragma unroll
    for (int i = 0; i < 4; i++)
        out[(size_t)(c0 + ty + (i << 3)) * R + r0 + tx] = t[tx][ty + (i << 3)];
}

// ---------------- head-sum of wq/wk columns into combined [1024][32] ----------------
__global__ void headsum_kernel(const float* __restrict__ wq, const float* __restrict__ bq,
                               const float* __restrict__ wk, const float* __restrict__ bk,
                               float* __restrict__ wqk, float* __restrict__ bqk)
{
    const int idx = blockIdx.x * blockDim.x + threadIdx.x;
    if (idx < D_MODEL * NHEAD) {
        const int d = idx >> 4, h = idx & 15;
        const float* pq = wq + (size_t)d * D_MODEL + h * DHEAD;
        const float* pk = wk + (size_t)d * D_MODEL + h * DHEAD;
        float sq = 0.f, sk = 0.f;
        #pragma unroll 8
        for (int i = 0; i < DHEAD; i++) { sq += pq[i]; sk += pk[i]; }
        wqk[d * 32 + h]      = sq;
        wqk[d * 32 + 16 + h] = sk;
    }
    if (idx < NHEAD) {
        float sq = 0.f, sk = 0.f;
        for (int i = 0; i < DHEAD; i++) {
            sq += bq[idx * DHEAD + i];
            sk += bk[idx * DHEAD + i];
        }
        bqk[idx] = sq; bqk[16 + idx] = sk;
    }
}

// ---------------- tiled skinny GEMM: C[8192,32] = xn @ wqk + bqk → qs|ks --------------
__global__ void __launch_bounds__(256)
qsks_gemm(const float* __restrict__ xn, const float* __restrict__ wqk,
          const float* __restrict__ bqk, float* __restrict__ qs, float* __restrict__ ks)
{
    __shared__ float Asm[32][132];
    __shared__ float Wsm[32][36];

    const int tx   = threadIdx.x;
    const int brow = blockIdx.x << 7;
    const int tm   = (tx >> 3) << 2;
    const int tn   = (tx & 7) << 2;

    float acc[4][4];
    #pragma unroll
    for (int i = 0; i < 4; i++)
        #pragma unroll
        for (int j = 0; j < 4; j++) acc[i][j] = 0.f;

    for (int k0 = 0; k0 < D_MODEL; k0 += 32) {
        #pragma unroll
        for (int t = 0; t < 4; t++) {
            const int idx = tx + (t << 8);
            const int r   = idx >> 3;
            const int c4  = (idx & 7) << 2;
            const float4 a4 = *(const float4*)(xn + (size_t)(brow + r) * D_MODEL + k0 + c4);
            Asm[c4 + 0][r] = a4.x; Asm[c4 + 1][r] = a4.y;
            Asm[c4 + 2][r] = a4.z; Asm[c4 + 3][r] = a4.w;
        }
        {
            const int r  = tx >> 3;
            const int c4 = (tx & 7) << 2;
            *(float4*)&Wsm[r][c4] = *(const float4*)(wqk + (size_t)(k0 + r) * 32 + c4);
        }
        __syncthreads();

        #pragma unroll
        for (int kk = 0; kk < 32; kk++) {
            float ra[4], rb[4];
            *(float4*)ra = *(const float4*)&Asm[kk][tm];
            *(float4*)rb = *(const float4*)&Wsm[kk][tn];
            #pragma unroll
            for (int i = 0; i < 4; i++)
                #pragma unroll
                for (int j = 0; j < 4; j++)
                    acc[i][j] = fmaf(ra[i], rb[j], acc[i][j]);
        }
        __syncthreads();
    }

    #pragma unroll
    for (int i = 0; i < 4; i++) {
        const size_t row = (size_t)(brow + tm + i);
        #pragma unroll
        for (int j = 0; j < 4; j++) {
            const int c = tn + j;
            const float v = acc[i][j] + bqk[c];
            if (c < 16) qs[row * NHEAD + c]        = v;
            else        ks[row * NHEAD + (c - 16)] = v;
        }
    }
}

// ---------------- tcgen05 tf32 GEMM: C[M_TOK,N] = A[M_TOK,K] @ Wt^T + bias (+resid)(relu)
// A row-major [M_TOK,K]; Wt row-major [N,K] (pre-transposed weights).
// Tile 128x128, K-chunks of 32 (4 x K8 tf32 MMA per chunk), double-buffered smem.
#define TC_SMEM_A(buf)  (1024 + (buf) * 16384)
#define TC_SMEM_B(buf)  (33792 + (buf) * 16384)
#define TC_SMEM_TOTAL   66560
#define TC_IDESC  ((1u << 4) | (2u << 7) | (2u << 10) | (16u << 17) | (8u << 24))

template<bool RELU, bool RESID>
__global__ void __launch_bounds__(256, 2)
sgemm_tc(const float* __restrict__ A, const float* __restrict__ Wt,
         const float* __restrict__ bias, const float* __restrict__ resid,
         float* __restrict__ C, int N, int K)
{
#if HAS_TCGEN05
    extern __shared__ char sm[];
    const uint32_t smem_base = smem_to_u32(sm);
    const int tx = threadIdx.x;
    const int brow = blockIdx.y << 7;
    const int bcol = blockIdx.x << 7;

    // TMEM alloc (warp 0), 128 cols for D
    if ((tx >> 5) == 0) TCGEN05_ALLOC(smem_base + 0, 128);
    if (tx == 0) {
        MBARRIER_INIT(smem_base + 8, 1);
        MBARRIER_INIT(smem_base + 16, 1);
    }
    __syncthreads();
    if ((tx >> 5) == 0) TCGEN05_RELINQUISH();
    uint32_t tmem_base;
    asm volatile("ld.shared.b32 %0, [%1];" : "=r"(tmem_base) : "r"(smem_base + 0));

    const float* Abase = A  + (size_t)brow * K;
    const float* Bbase = Wt + (size_t)bcol * K;

    int ph0 = 0, ph1 = 0;
    const int nchunk = K >> 5;

    for (int i = 0; i < nchunk; i++) {
        const int buf = i & 1;
        if (i >= 2) {
            if (buf == 0) { MBAR_WAIT(smem_base + 8,  ph0); ph0 ^= 1; }
            else          { MBAR_WAIT(smem_base + 16, ph1); ph1 ^= 1; }
        }
        const int k0 = i << 5;
        char* sA = sm + TC_SMEM_A(buf);
        char* sB = sm + TC_SMEM_B(buf);
        #pragma unroll
        for (int t = 0; t < 4; t++) {
            const int idx = tx + (t << 8);       // 0..1023 float4s
            const int r   = idx >> 3;
            const int c   = (idx & 7) << 2;      // float col within chunk
            const float4 a = *(const float4*)(Abase + (size_t)r * K + k0 + c);
            const float4 b = *(const float4*)(Bbase + (size_t)r * K + k0 + c);
            uint4 ua, ub;
            ua.x = tf32_of(a.x); ua.y = tf32_of(a.y); ua.z = tf32_of(a.z); ua.w = tf32_of(a.w);
            ub.x = tf32_of(b.x); ub.y = tf32_of(b.y); ub.z = tf32_of(b.z); ub.w = tf32_of(b.w);
            const uint32_t off = SMEM_SWIZZLE_128B((uint32_t)(r * 128 + c * 4));
            *(uint4*)(sA + off) = ua;
            *(uint4*)(sB + off) = ub;
        }
        FENCE_PROXY_ASYNC();
        __syncthreads();

        if (tx == 0) {
            TC_FENCE_AFTER();
            const uint64_t ad = MAKE_SMEM_DESC(smem_base + TC_SMEM_A(buf));
            const uint64_t bd = MAKE_SMEM_DESC(smem_base + TC_SMEM_B(buf));
            #pragma unroll
            for (int s = 0; s < 4; s++)
                mma_tf32_ss(tmem_base, ad + 2 * s, bd + 2 * s, TC_IDESC,
                            (i | s) != 0 ? 1u : 0u);
            TC_COMMIT(smem_base + 8 + buf * 8);
        }
    }

    MBAR_WAIT(smem_base + 8,  ph0);
    MBAR_WAIT(smem_base + 16, ph1);
    TC_FENCE_AFTER();

    // epilogue: 8 warps; warp w covers rows (w&3)*32+lane, cols (w>>2)*64..+63
    {
        const int w    = tx >> 5;
        const int lane = tx & 31;
        const int half = w >> 2;
        const int colb = half << 6;
        uint32_t d[64];
        TCGEN05_LD_32X32B_X32(d,      tmem_base + colb);
        TCGEN05_LD_32X32B_X32(d + 32, tmem_base + colb + 32);
        TCGEN05_WAIT_LD();

        const int row = brow + ((w & 3) << 5) + lane;
        float* Crow = C + (size_t)row * N + bcol + colb;
        const float* Rrow = resid + (size_t)row * N + bcol + colb;
        const float* brow_p = bias + bcol + colb;
        #pragma unroll
        for (int j = 0; j < 64; j += 4) {
            const float4 bv = *(const float4*)(brow_p + j);
            float4 o;
            o.x = __uint_as_float(d[j + 0]) + bv.x;
            o.y = __uint_as_float(d[j + 1]) + bv.y;
            o.z = __uint_as_float(d[j + 2]) + bv.z;
            o.w = __uint_as_float(d[j + 3]) + bv.w;
            if (RESID) {
                const float4 rv = *(const float4*)(Rrow + j);
                o.x += rv.x; o.y += rv.y; o.z += rv.z; o.w += rv.w;
            }
            if (RELU) {
                o.x = fmaxf(o.x, 0.f); o.y = fmaxf(o.y, 0.f);
                o.z = fmaxf(o.z, 0.f); o.w = fmaxf(o.w, 0.f);
            }
            *(float4*)(Crow + j) = o;
        }
    }

    __syncthreads();
    if ((tx >> 5) == 0) TCGEN05_DEALLOC(tmem_base, 128);
#endif // HAS_TCGEN05
}

// ---------------- attention: rank-1 scores + online softmax + P@V (f32x2) ------------
__global__ void __launch_bounds__(256)
attn_kernel(const float* __restrict__ qs, const float* __restrict__ ks,
            const float* __restrict__ v, const unsigned char* __restrict__ mask,
            float* __restrict__ o)
{
    __shared__ float Vs[64][68];
    __shared__ float Ps[64][68];
    __shared__ float kss[64];
    __shared__ float qss[64];
    __shared__ unsigned char msk[64];

    const int tx = threadIdx.x;
    const int bh = blockIdx.y;
    const int b  = bh >> 4;
    const int h  = bh & 15;
    const int m0 = blockIdx.x << 6;

    const int row = tx >> 2;
    const int qd  = tx & 3;
    const int c0  = qd << 4;

    if (tx < 64)
        qss[tx] = qs[((size_t)(m0 + tx) * BATCH + b) * NHEAD + h];

    float m_run = -1e30f, l_run = 0.f;
    ull acc[8];
    #pragma unroll
    for (int j = 0; j < 8; j++) acc[j] = 0ULL;

    for (int n0 = 0; n0 < SEQ; n0 += 64) {
        __syncthreads();
        if (tx < 64) {
            kss[tx] = ks[((size_t)(n0 + tx) * BATCH + b) * NHEAD + h];
            msk[tx] = mask[(size_t)(n0 + tx) * BATCH + b];
        }
        #pragma unroll
        for (int t = 0; t < 4; t++) {
            const int idx = tx + (t << 8);
            const int n   = idx >> 4;
            const int j4  = (idx & 15) << 2;
            *(float4*)&Vs[n][j4] =
                *(const float4*)(v + ((size_t)(n0 + n) * BATCH + b) * D_MODEL + h * DHEAD + j4);
        }
        __syncthreads();

        const float qv = qss[row];
        float s[16];
        float tmax = -1e30f;
        #pragma unroll
        for (int cc = 0; cc < 16; cc++) {
            const float sv = msk[c0 + cc] ? -1000.0f : qv * kss[c0 + cc];
            s[cc] = sv;
            tmax = fmaxf(tmax, sv);
        }
        tmax = fmaxf(tmax, __shfl_xor_sync(0xffffffffu, tmax, 1));
        tmax = fmaxf(tmax, __shfl_xor_sync(0xffffffffu, tmax, 2));
        const float m_new = fmaxf(m_run, tmax);

        float psum = 0.f;
        #pragma unroll
        for (int cc = 0; cc < 16; cc++) {
            const float p = __expf(s[cc] - m_new);
            Ps[row][c0 + cc] = p;
            psum += p;
        }
        psum += __shfl_xor_sync(0xffffffffu, psum, 1);
        psum += __shfl_xor_sync(0xffffffffu, psum, 2);

        const float scale = __expf(m_run - m_new);
        l_run = l_run * scale + psum;
        m_run = m_new;
        const ull sc2 = pack2(scale, scale);
        #pragma unroll
        for (int j = 0; j < 8; j++) mul2(acc[j], sc2);
        __syncthreads();

        #pragma unroll 4
        for (int n = 0; n < 64; n++) {
            const float pv = Ps[row][n];
            const ull pd = pack2(pv, pv);
            const ulonglong2 v01 = *(const ulonglong2*)&Vs[n][c0];
            const ulonglong2 v23 = *(const ulonglong2*)&Vs[n][c0 + 4];
            const ulonglong2 v45 = *(const ulonglong2*)&Vs[n][c0 + 8];
            const ulonglong2 v67 = *(const ulonglong2*)&Vs[n][c0 + 12];
            fma2(acc[0], pd, v01.x); fma2(acc[1], pd, v01.y);
            fma2(acc[2], pd, v23.x); fma2(acc[3], pd, v23.y);
            fma2(acc[4], pd, v45.x); fma2(acc[5], pd, v45.y);
            fma2(acc[6], pd, v67.x); fma2(acc[7], pd, v67.y);
        }
    }

    const float inv = 1.f / l_run;
    const size_t r = (size_t)(m0 + row) * BATCH + b;
    #pragma unroll
    for (int j = 0; j < 4; j++) {
        const float2 pa = unpack2(acc[2 * j]);
        const float2 pb = unpack2(acc[2 * j + 1]);
        float4 ov;
        ov.x = pa.x * inv; ov.y = pa.y * inv;
        ov.z = pb.x * inv; ov.w = pb.y * inv;
        *(float4*)(o + r * D_MODEL + h * DHEAD + c0 + (j << 2)) = ov;
    }
}

// ---------------- launcher ----------------
extern "C" void kernel_launch(void* const* d_in, const int* in_sizes, int n_in,
                              void* d_out, int out_size)
{
    const float* x     = (const float*)d_in[0];
    const unsigned char* mask = (const unsigned char*)d_in[1];
    const float* ln1_g = (const float*)d_in[2];
    const float* ln1_b = (const float*)d_in[3];
    const float* wq    = (const float*)d_in[4];
    const float* bq    = (const float*)d_in[5];
    const float* wk    = (const float*)d_in[6];
    const float* bk    = (const float*)d_in[7];
    const float* wv    = (const float*)d_in[8];
    const float* bv    = (const float*)d_in[9];
    const float* wo    = (const float*)d_in[10];
    const float* bo    = (const float*)d_in[11];
    const float* ln2_g = (const float*)d_in[12];
    const float* ln2_b = (const float*)d_in[13];
    const float* w1    = (const float*)d_in[14];
    const float* b1    = (const float*)d_in[15];
    const float* w2    = (const float*)d_in[16];
    const float* b2    = (const float*)d_in[17];
    float* out = (float*)d_out;

    float* scratch = nullptr;
    cudaGetSymbolAddress((void**)&scratch, g_scratch);
    float* xn   = scratch + OFF_XN;
    float* vbuf = scratch + OFF_V;
    float* pool = scratch + OFF_POOL;
    float* x2   = scratch + OFF_X2;
    float* hbuf = scratch + OFF_H;
    float* qsb  = scratch + OFF_QS;
    float* ksb  = scratch + OFF_KS;
    float* wqk  = scratch + OFF_WQK;
    float* bqk  = scratch + OFF_BQK;
    float* wvt  = scratch + OFF_WVT;
    float* wot  = scratch + OFF_WOT;
    float* w1t  = scratch + OFF_W1T;
    float* w2t  = scratch + OFF_W2T;

    cudaFuncSetAttribute(sgemm_tc<false, false>, cudaFuncAttributeMaxDynamicSharedMemorySize, TC_SMEM_TOTAL);
    cudaFuncSetAttribute(sgemm_tc<false, true>,  cudaFuncAttributeMaxDynamicSharedMemorySize, TC_SMEM_TOTAL);
    cudaFuncSetAttribute(sgemm_tc<true, false>,  cudaFuncAttributeMaxDynamicSharedMemorySize, TC_SMEM_TOTAL);

    // weight transposes (per launch; ~60us total)
    transpose_kernel<<<dim3(32, 32),  256>>>(wv, wvt, D_MODEL, D_MODEL);
    transpose_kernel<<<dim3(32, 32),  256>>>(wo, wot, D_MODEL, D_MODEL);
    transpose_kernel<<<dim3(128, 32), 256>>>(w1, w1t, D_MODEL, FF_DIM);
    transpose_kernel<<<dim3(32, 128), 256>>>(w2, w2t, FF_DIM, D_MODEL);

    // 1. xn = LN1(x)
    ln_kernel<<<M_TOK, 256>>>(x, ln1_g, ln1_b, xn);
    // 2. fold head-sums of wq/wk (rank-1 attention)
    headsum_kernel<<<64, 256>>>(wq, bq, wk, bk, wqk, bqk);
    // 3. v = xn @ wv + bv   (tcgen05 tf32)
    sgemm_tc<false, false><<<dim3(D_MODEL / 128, M_TOK / 128), 256, TC_SMEM_TOTAL>>>(
        xn, wvt, bv, nullptr, vbuf, D_MODEL, D_MODEL);
    // 4. qs/ks = xn @ wqk + bqk
    qsks_gemm<<<M_TOK / 128, 256>>>(xn, wqk, bqk, qsb, ksb);
    // 5. pooled = softmax(qs ⊗ ks, masked) @ v
    attn_kernel<<<dim3(SEQ / 64, BATCH * NHEAD), 256>>>(qsb, ksb, vbuf, mask, pool);
    // 6. x2 = pooled @ wo + bo + x
    sgemm_tc<false, true><<<dim3(D_MODEL / 128, M_TOK / 128), 256, TC_SMEM_TOTAL>>>(
        pool, wot, bo, x, x2, D_MODEL, D_MODEL);
    // 7. xn = LN2(x2)
    ln_kernel<<<M_TOK, 256>>>(x2, ln2_g, ln2_b, xn);
    // 8. h = relu(xn @ w1 + b1)
    sgemm_tc<true, false><<<dim3(FF_DIM / 128, M_TOK / 128), 256, TC_SMEM_TOTAL>>>(
        xn, w1t, b1, nullptr, hbuf, FF_DIM, D_MODEL);
    // 9. out = h @ w2 + b2 + x2
    sgemm_tc<false, true><<<dim3(D_MODEL / 128, M_TOK / 128), 256, TC_SMEM_TOTAL>>>(
        hbuf, w2t, b2, x2, out, D_MODEL, FF_DIM);
}

// round 7
// speedup vs baseline: 8.7033x; 3.5798x over previous
#include <cuda_runtime.h>
#include <cstddef>
#include <cstdint>

// Problem constants
#define M_TOK   8192     // M*B token rows
#define D_MODEL 1024
#define FF_DIM  4096
#define NHEAD   16
#define DHEAD   64
#define SEQ     1024
#define BATCH   8

// tcgen05 is arch-SPECIFIC (sm_103a). nvcc also runs a generic compute_103 PTX
// pass where these instructions don't exist — compile a stub there.
#if defined(__CUDA_ARCH__) && (defined(__CUDA_ARCH_FEAT_SM103_ALL) || defined(__CUDA_ARCH_SPECIFIC__))
#define HAS_TCGEN05 1
#else
#define HAS_TCGEN05 0
#endif

typedef unsigned long long ull;

// ---------------- packed f32x2 helpers ----------------
__device__ __forceinline__ ull pack2(float x, float y) {
    ull r; asm("mov.b64 %0, {%1, %2};" : "=l"(r) : "f"(x), "f"(y)); return r;
}
__device__ __forceinline__ float2 unpack2(ull v) {
    float2 r; asm("mov.b64 {%0, %1}, %2;" : "=f"(r.x), "=f"(r.y) : "l"(v)); return r;
}
__device__ __forceinline__ void fma2(ull& d, ull a, ull b) {
    asm("fma.rn.f32x2 %0, %1, %2, %0;" : "+l"(d) : "l"(a), "l"(b));
}
__device__ __forceinline__ void mul2(ull& d, ull a) {
    asm("mul.rn.f32x2 %0, %0, %1;" : "+l"(d) : "l"(a));
}

// ---------------- tcgen05 / TMA helpers ----------------
static constexpr uint64_t SMEM_DESC_BASE_SW128 =
    (uint64_t(2)  << 61) | (uint64_t(1) << 46) | (uint64_t(64) << 32) | (uint64_t(1) << 16);
#define MAKE_SMEM_DESC(base_addr) \
    (SMEM_DESC_BASE_SW128 | ((uint64_t)((base_addr) >> 4) & 0x3FFF))

__device__ __forceinline__ uint32_t smem_to_u32(const void* p) {
    uint32_t a;
    asm("{ .reg .u64 t; cvta.to.shared.u64 t, %1; cvt.u32.u64 %0, t; }" : "=r"(a) : "l"(p));
    return a;
}
__device__ __forceinline__ uint32_t tf32_of(float f) {
    uint32_t r; asm("cvt.rna.tf32.f32 %0, %1;" : "=r"(r) : "f"(f)); return r;
}
__device__ __forceinline__ float tf32f(float f) {
    return __uint_as_float(tf32_of(f));
}

#if HAS_TCGEN05
#define TCGEN05_ALLOC(smem_res, nCols) \
    asm volatile("tcgen05.alloc.cta_group::1.sync.aligned.shared::cta.b32 [%0], %1;" \
                 :: "r"((uint32_t)(smem_res)), "r"((uint32_t)(nCols)) : "memory")
#define TCGEN05_DEALLOC(tmem, nCols) \
    asm volatile("tcgen05.dealloc.cta_group::1.sync.aligned.b32 %0, %1;" \
                 :: "r"(tmem), "r"((uint32_t)(nCols)))
#define TCGEN05_RELINQUISH() \
    asm volatile("tcgen05.relinquish_alloc_permit.cta_group::1.sync.aligned;")
#define TCGEN05_WAIT_LD() asm volatile("tcgen05.wait::ld.sync.aligned;" ::: "memory")
#define TC_FENCE_AFTER()  asm volatile("tcgen05.fence::after_thread_sync;" ::: "memory")
#define TC_COMMIT(mbar) \
    asm volatile("tcgen05.commit.cta_group::1.mbarrier::arrive::one.shared::cluster.b64 [%0];" \
                 :: "r"((uint32_t)(mbar)) : "memory")
#endif

#define MBARRIER_INIT(mbar, cnt) \
    asm volatile("mbarrier.init.shared.b64 [%0], %1;" :: "r"((uint32_t)(mbar)), "r"((uint32_t)(cnt)) : "memory")
#define MBARRIER_EXPECT_TX(mbar, bytes) \
    asm volatile("mbarrier.arrive.expect_tx.shared.b64 _, [%0], %1;" \
                 :: "r"((uint32_t)(mbar)), "r"((uint32_t)(bytes)) : "memory")
#define MBAR_WAIT(mbar, ph) \
    asm volatile("{\n\t.reg .pred P;\n\tWL%=:\n\t" \
                 "mbarrier.try_wait.parity.acquire.cta.shared::cta.b64 P, [%0], %1, 0x989680;\n\t" \
                 "@!P bra WL%=;\n\t}" :: "r"((uint32_t)(mbar)), "r"((uint32_t)(ph)) : "memory")
#define BULK_G2S(dst, src, bytes, mbar) \
    asm volatile("cp.async.bulk.shared::cta.global.mbarrier::complete_tx::bytes [%0], [%1], %2, [%3];" \
                 :: "r"((uint32_t)(dst)), "l"(src), "r"((uint32_t)(bytes)), "r"((uint32_t)(mbar)) : "memory")

#if HAS_TCGEN05
#define TCGEN05_LD_32X32B_X32(r, tmem_addr) \
    asm volatile( \
        "tcgen05.ld.sync.aligned.32x32b.x32.b32 " \
        "{%0, %1, %2, %3, %4, %5, %6, %7, " \
        " %8, %9, %10, %11, %12, %13, %14, %15, " \
        " %16, %17, %18, %19, %20, %21, %22, %23, " \
        " %24, %25, %26, %27, %28, %29, %30, %31}, [%32];" \
        : "=r"((r)[0]),  "=r"((r)[1]),  "=r"((r)[2]),  "=r"((r)[3]), \
          "=r"((r)[4]),  "=r"((r)[5]),  "=r"((r)[6]),  "=r"((r)[7]), \
          "=r"((r)[8]),  "=r"((r)[9]),  "=r"((r)[10]), "=r"((r)[11]), \
          "=r"((r)[12]), "=r"((r)[13]), "=r"((r)[14]), "=r"((r)[15]), \
          "=r"((r)[16]), "=r"((r)[17]), "=r"((r)[18]), "=r"((r)[19]), \
          "=r"((r)[20]), "=r"((r)[21]), "=r"((r)[22]), "=r"((r)[23]), \
          "=r"((r)[24]), "=r"((r)[25]), "=r"((r)[26]), "=r"((r)[27]), \
          "=r"((r)[28]), "=r"((r)[29]), "=r"((r)[30]), "=r"((r)[31]) \
        : "r"(tmem_addr))

// tf32 SS MMA, cg1. idesc: dfmt F32(1<<4) | a TF32(2<<7) | b TF32(2<<10) | (N/8)<<17 | (M/16)<<24
__device__ __forceinline__ void mma_tf32_ss(uint32_t d_tmem, uint64_t a_desc, uint64_t b_desc,
                                            uint32_t idesc, uint32_t en)
{
    asm volatile(
        "{\n\t"
        ".reg .pred p;\n\t"
        "setp.ne.u32 p, %5, 0;\n\t"
        "tcgen05.mma.cta_group::1.kind::tf32 [%0], %1, %2, %3, {%4, %4, %4, %4}, p;\n\t"
        "}"
        :: "r"(d_tmem), "l"(a_desc), "l"(b_desc), "r"(idesc), "r"(0u), "r"(en)
        : "memory");
}
#endif

// ================= chunked + pre-swizzled GEMM operand layout =================
// element (row, k) of an operand with R total rows lives at float index:
//   ((k>>5)*R + row)*32 + (((k>>2)&7) ^ (row&7))*4 + (k&3)
// so each 32-K chunk is a contiguous [R][128B] block whose rows carry the SW128
// 16B-block permutation. One cp.async.bulk per chunk lands MMA-ready in smem.
__device__ __forceinline__ size_t chunk_idx(int row, int k, int R) {
    return ((size_t)(k >> 5) * R + row) * 32 + ((((k >> 2) & 7) ^ (row & 7)) << 2) + (k & 3);
}

// ---------------- scratch (static device memory) ----------------
static const size_t OFF_XN   = 0;
static const size_t OFF_V    = 8388608;
static const size_t OFF_POOL = 16777216;
static const size_t OFF_X2   = 25165824;
static const size_t OFF_H    = 33554432;
static const size_t OFF_QS   = 67108864;
static const size_t OFF_KS   = 67239936;
static const size_t OFF_WQK  = 67371008;   // [1024][32]
static const size_t OFF_BQK  = 67403776;   // [32]
static const size_t OFF_WVT  = 67403808;   // chunked [32][1024][32]
static const size_t OFF_WOT  = 68452384;
static const size_t OFF_W1T  = 69500960;   // chunked [32][4096][32]
static const size_t OFF_W2T  = 73695264;   // chunked [128][1024][32]
static const size_t SCRATCH_FLOATS = 77889568;

__device__ float g_scratch[SCRATCH_FLOATS];

// ---------------- LayerNorm: row-major in -> chunked tf32-rounded out --------
__global__ void __launch_bounds__(256)
ln_kernel(const float* __restrict__ x, const float* __restrict__ g,
          const float* __restrict__ bta, float* __restrict__ y)
{
    const int row = blockIdx.x;
    const int tx  = threadIdx.x;
    const float4 v = ((const float4*)(x + (size_t)row * D_MODEL))[tx];

    float s  = v.x + v.y + v.z + v.w;
    float sq = v.x * v.x + v.y * v.y + v.z * v.z + v.w * v.w;
    #pragma unroll
    for (int o = 16; o; o >>= 1) {
        s  += __shfl_xor_sync(0xffffffffu, s,  o);
        sq += __shfl_xor_sync(0xffffffffu, sq, o);
    }
    __shared__ float ss[8], ssq[8];
    const int w = tx >> 5, l = tx & 31;
    if (l == 0) { ss[w] = s; ssq[w] = sq; }
    __syncthreads();
    s = 0.f; sq = 0.f;
    #pragma unroll
    for (int i = 0; i < 8; i++) { s += ss[i]; sq += ssq[i]; }

    const float mean = s * (1.f / D_MODEL);
    const float var  = sq * (1.f / D_MODEL) - mean * mean;
    const float rstd = rsqrtf(var + 1e-5f);

    const float4 gv = ((const float4*)g)[tx];
    const float4 bv = ((const float4*)bta)[tx];
    float4 o4;
    o4.x = tf32f((v.x - mean) * rstd * gv.x + bv.x);
    o4.y = tf32f((v.y - mean) * rstd * gv.y + bv.y);
    o4.z = tf32f((v.z - mean) * rstd * gv.z + bv.z);
    o4.w = tf32f((v.w - mean) * rstd * gv.w + bv.w);
    // chunked write: k = 4*tx
    const size_t oidx = ((size_t)(tx >> 3) * M_TOK + row) * 32 + (((tx & 7) ^ (row & 7)) << 2);
    *(float4*)(y + oidx) = o4;
}

// ---------------- transpose into chunked layout: in[K][N] -> outT(n,k) -------
__global__ void __launch_bounds__(256)
transpose_kernel(const float* __restrict__ in, float* __restrict__ out, int K, int N)
{
    __shared__ float t[32][33];
    const int k0 = blockIdx.y << 5;
    const int n0 = blockIdx.x << 5;
    const int tx = threadIdx.x & 31;
    const int ty = threadIdx.x >> 5;   // 0..7
    #pragma unroll
    for (int i = 0; i < 4; i++)
        t[ty + (i << 3)][tx] = in[(size_t)(k0 + ty + (i << 3)) * N + n0 + tx];
    __syncthreads();
    // write element (n = n0+ty+8i, k = k0+tx), tf32-rounded, chunked
    #pragma unroll
    for (int i = 0; i < 4; i++) {
        const int n = n0 + ty + (i << 3);
        const int k = k0 + tx;
        out[chunk_idx(n, k, N)] = tf32f(t[tx][ty + (i << 3)]);
    }
}

// ---------------- head-sum of wq/wk columns into combined [1024][32] ---------
__global__ void headsum_kernel(const float* __restrict__ wq, const float* __restrict__ bq,
                               const float* __restrict__ wk, const float* __restrict__ bk,
                               float* __restrict__ wqk, float* __restrict__ bqk)
{
    const int idx = blockIdx.x * blockDim.x + threadIdx.x;
    if (idx < D_MODEL * NHEAD) {
        const int d = idx >> 4, h = idx & 15;
        const float* pq = wq + (size_t)d * D_MODEL + h * DHEAD;
        const float* pk = wk + (size_t)d * D_MODEL + h * DHEAD;
        float sq = 0.f, sk = 0.f;
        #pragma unroll 8
        for (int i = 0; i < DHEAD; i++) { sq += pq[i]; sk += pk[i]; }
        wqk[d * 32 + h]      = sq;
        wqk[d * 32 + 16 + h] = sk;
    }
    if (idx < NHEAD) {
        float sq = 0.f, sk = 0.f;
        for (int i = 0; i < DHEAD; i++) {
            sq += bq[idx * DHEAD + i];
            sk += bk[idx * DHEAD + i];
        }
        bqk[idx] = sq; bqk[16 + idx] = sk;
    }
}

// ---------------- skinny GEMM: C[8192,32] = xn(chunked) @ wqk + bqk → qs|ks ---
__global__ void __launch_bounds__(256)
qsks_gemm(const float* __restrict__ xn, const float* __restrict__ wqk,
          const float* __restrict__ bqk, float* __restrict__ qs, float* __restrict__ ks)
{
    __shared__ float Asm[32][132];
    __shared__ float Wsm[32][36];

    const int tx   = threadIdx.x;
    const int brow = blockIdx.x << 7;
    const int tm   = (tx >> 3) << 2;
    const int tn   = (tx & 7) << 2;

    float acc[4][4];
    #pragma unroll
    for (int i = 0; i < 4; i++)
        #pragma unroll
        for (int j = 0; j < 4; j++) acc[i][j] = 0.f;

    for (int k0 = 0; k0 < D_MODEL; k0 += 32) {
        const int chk = k0 >> 5;
        #pragma unroll
        for (int t = 0; t < 4; t++) {
            const int idx = tx + (t << 8);
            const int r   = idx >> 3;
            const int c4  = (idx & 7) << 2;
            // chunked read: row brow+r, k-block (c4>>2) permuted by row&7
            const size_t gidx = ((size_t)chk * M_TOK + brow + r) * 32 +
                                ((((c4 >> 2)) ^ (r & 7)) << 2);
            const float4 a4 = *(const float4*)(xn + gidx);
            Asm[c4 + 0][r] = a4.x; Asm[c4 + 1][r] = a4.y;
            Asm[c4 + 2][r] = a4.z; Asm[c4 + 3][r] = a4.w;
        }
        {
            const int r  = tx >> 3;
            const int c4 = (tx & 7) << 2;
            *(float4*)&Wsm[r][c4] = *(const float4*)(wqk + (size_t)(k0 + r) * 32 + c4);
        }
        __syncthreads();

        #pragma unroll
        for (int kk = 0; kk < 32; kk++) {
            float ra[4], rb[4];
            *(float4*)ra = *(const float4*)&Asm[kk][tm];
            *(float4*)rb = *(const float4*)&Wsm[kk][tn];
            #pragma unroll
            for (int i = 0; i < 4; i++)
                #pragma unroll
                for (int j = 0; j < 4; j++)
                    acc[i][j] = fmaf(ra[i], rb[j], acc[i][j]);
        }
        __syncthreads();
    }

    #pragma unroll
    for (int i = 0; i < 4; i++) {
        const size_t row = (size_t)(brow + tm + i);
        #pragma unroll
        for (int j = 0; j < 4; j++) {
            const int c = tn + j;
            const float v = acc[i][j] + bqk[c];
            if (c < 16) qs[row * NHEAD + c]        = v;
            else        ks[row * NHEAD + (c - 16)] = v;
        }
    }
}

// ======== tcgen05 tf32 GEMM: 256x256 supertile, 3-stage cp.async.bulk pipeline ========
// A chunked [K/32][M_TOK][32] (pre-rounded+pre-swizzled); Wt chunked [K/32][N][32].
// C row-major (or chunked for CHUNKOUT). bias/resid row-major fp32.
#define TC_STAGES   3
#define TC_HDR      1024
#define TC_STAGE_SZ 65536
#define TC_SMEM_TOTAL (TC_HDR + TC_STAGES * TC_STAGE_SZ)   // 197632
#define TC_IDESC  ((1u << 4) | (2u << 7) | (2u << 10) | (32u << 17) | (8u << 24))  // N=256, M=128

template<bool RELU, bool RESID, bool CHUNKOUT>
__global__ void __launch_bounds__(256)
sgemm_tc(const float* __restrict__ A, const float* __restrict__ Wt,
         const float* __restrict__ bias, const float* __restrict__ resid,
         float* __restrict__ C, int N, int K)
{
#if HAS_TCGEN05
    extern __shared__ char sm[];
    const uint32_t sb = smem_to_u32(sm);
    const int tx = threadIdx.x;
    const int brow = blockIdx.y << 8;   // 256 M rows
    const int bcol = blockIdx.x << 8;   // 256 N cols

    if ((tx >> 5) == 0) TCGEN05_ALLOC(sb, 512);
    if (tx == 0) {
        #pragma unroll
        for (int s = 0; s < TC_STAGES; s++) {
            MBARRIER_INIT(sb + 8 + s * 8, 1);    // full[s]
            MBARRIER_INIT(sb + 32 + s * 8, 1);   // done[s]
        }
    }
    __syncthreads();
    if ((tx >> 5) == 0) TCGEN05_RELINQUISH();
    uint32_t tmem;
    asm volatile("ld.shared.b32 %0, [%1];" : "=r"(tmem) : "r"(sb));

    const int nchunk = K >> 5;

    if (tx == 0) {
        TC_FENCE_AFTER();
        // prologue fills
        #pragma unroll
        for (int i = 0; i < TC_STAGES; i++) {
            const int s = i;
            const uint32_t full = sb + 8 + s * 8;
            MBARRIER_EXPECT_TX(full, 2 * 32768);
            BULK_G2S(sb + TC_HDR + s * TC_STAGE_SZ,
                     A + ((size_t)i * M_TOK + brow) * 32, 32768, full);
            BULK_G2S(sb + TC_HDR + s * TC_STAGE_SZ + 32768,
                     Wt + ((size_t)i * N + bcol) * 32, 32768, full);
        }
        for (int i = 0; i < nchunk; i++) {
            const int s = i % TC_STAGES;
            const int ph = (i / TC_STAGES) & 1;
            MBAR_WAIT(sb + 8 + s * 8, ph);    // data ready
            const uint32_t abase = sb + TC_HDR + s * TC_STAGE_SZ;
            const uint64_t ad0 = MAKE_SMEM_DESC(abase);
            const uint64_t ad1 = MAKE_SMEM_DESC(abase + 16384);
            const uint64_t bd  = MAKE_SMEM_DESC(abase + 32768);
            #pragma unroll
            for (int k8 = 0; k8 < 4; k8++) {
                const uint32_t en = (i | k8) ? 1u : 0u;
                mma_tf32_ss(tmem,       ad0 + 2 * k8, bd + 2 * k8, TC_IDESC, en);
                mma_tf32_ss(tmem + 256, ad1 + 2 * k8, bd + 2 * k8, TC_IDESC, en);
            }
            TC_COMMIT(sb + 32 + s * 8);       // done[s]
            const int j = i + TC_STAGES;
            if (j < nchunk) {
                MBAR_WAIT(sb + 32 + s * 8, ph);   // MMAs of chunk i finished
                const uint32_t full = sb + 8 + s * 8;
                MBARRIER_EXPECT_TX(full, 2 * 32768);
                BULK_G2S(abase,         A + ((size_t)j * M_TOK + brow) * 32, 32768, full);
                BULK_G2S(abase + 32768, Wt + ((size_t)j * N + bcol) * 32, 32768, full);
            }
        }
        // drain last three commits
        for (int j = nchunk - TC_STAGES; j < nchunk; j++) {
            const int s = j % TC_STAGES;
            MBAR_WAIT(sb + 32 + s * 8, (j / TC_STAGES) & 1);
        }
    }
    __syncthreads();
    TC_FENCE_AFTER();

    // epilogue: warp w: mtile = w>>2 (TMEM cols +256*mtile), row group (w&3)*32
    {
        const int w     = tx >> 5;
        const int lane  = tx & 31;
        const int mtile = w >> 2;
        const int row   = brow + (mtile << 7) + ((w & 3) << 5) + lane;
        const int rw7   = row & 7;
        #pragma unroll
        for (int slab = 0; slab < 4; slab++) {
            uint32_t d[64];
            TCGEN05_LD_32X32B_X32(d,      tmem + mtile * 256 + slab * 64);
            TCGEN05_LD_32X32B_X32(d + 32, tmem + mtile * 256 + slab * 64 + 32);
            TCGEN05_WAIT_LD();
            const int cb = bcol + slab * 64;
            const float* bp = bias + cb;
            const float* rp = RESID ? (resid + (size_t)row * N + cb) : nullptr;
            #pragma unroll
            for (int j = 0; j < 64; j += 4) {
                const float4 bv = *(const float4*)(bp + j);
                float4 o;
                o.x = __uint_as_float(d[j + 0]) + bv.x;
                o.y = __uint_as_float(d[j + 1]) + bv.y;
                o.z = __uint_as_float(d[j + 2]) + bv.z;
                o.w = __uint_as_float(d[j + 3]) + bv.w;
                if (RESID) {
                    const float4 rv = *(const float4*)(rp + j);
                    o.x += rv.x; o.y += rv.y; o.z += rv.z; o.w += rv.w;
                }
                if (RELU) {
                    o.x = fmaxf(o.x, 0.f); o.y = fmaxf(o.y, 0.f);
                    o.z = fmaxf(o.z, 0.f); o.w = fmaxf(o.w, 0.f);
                }
                if (CHUNKOUT) {
                    const int col = cb + j;
                    float4 q;
                    q.x = tf32f(o.x); q.y = tf32f(o.y); q.z = tf32f(o.z); q.w = tf32f(o.w);
                    const size_t oidx = ((size_t)(col >> 5) * M_TOK + row) * 32 +
                                        ((((col >> 2) & 7) ^ rw7) << 2);
                    *(float4*)(C + oidx) = q;
                } else {
                    *(float4*)(C + (size_t)row * N + cb + j) = o;
                }
            }
        }
    }

    __syncthreads();
    if ((tx >> 5) == 0) TCGEN05_DEALLOC(tmem, 512);
#endif // HAS_TCGEN05
}

// ---------------- attention: rank-1 scores + online softmax + P@V -------------
// 256 queries per block, 4 q per thread (V smem rows reused 4x). Output pool is
// tf32-rounded + chunked (feeds the WO GEMM as A operand).
#define ATTN_SMEM_FLOATS (64*68 + 256*68 + 256 + 64 + 16)
__global__ void __launch_bounds__(256)
attn_kernel(const float* __restrict__ qs, const float* __restrict__ ks,
            const float* __restrict__ v, const unsigned char* __restrict__ mask,
            float* __restrict__ pool)
{
    extern __shared__ float dyn[];
    float* Vs  = dyn;                      // [64][68]
    float* Ps  = Vs + 64 * 68;             // [256][68]
    float* qss = Ps + 256 * 68;            // [256]
    float* kss = qss + 256;                // [64]
    unsigned char* msk = (unsigned char*)(kss + 64);   // [64]

    const int tx = threadIdx.x;
    const int bh = blockIdx.y;
    const int b  = bh >> 4;
    const int h  = bh & 15;
    const int m0 = blockIdx.x << 8;        // 256 queries

    const int qd = tx & 3;
    const int qr = tx >> 2;                // 0..63
    const int c0 = qd << 4;

    qss[tx] = qs[((size_t)(m0 + tx) * BATCH + b) * NHEAD + h];

    float m_run[4], l_run[4];
    ull acc[4][8];
    #pragma unroll
    for (int u = 0; u < 4; u++) {
        m_run[u] = -1e30f; l_run[u] = 0.f;
        #pragma unroll
        for (int j = 0; j < 8; j++) acc[u][j] = 0ULL;
    }

    for (int n0 = 0; n0 < SEQ; n0 += 64) {
        __syncthreads();   // previous tile fully consumed
        if (tx < 64) {
            kss[tx] = ks[((size_t)(n0 + tx) * BATCH + b) * NHEAD + h];
            msk[tx] = mask[(size_t)(n0 + tx) * BATCH + b];
        }
        #pragma unroll
        for (int t = 0; t < 4; t++) {
            const int idx = tx + (t << 8);
            const int n   = idx >> 4;
            const int j4  = (idx & 15) << 2;
            *(float4*)&Vs[n * 68 + j4] =
                *(const float4*)(v + ((size_t)(n0 + n) * BATCH + b) * D_MODEL + h * DHEAD + j4);
        }
        __syncthreads();

        float kv[16];
        unsigned mb = 0;
        #pragma unroll
        for (int cc = 0; cc < 16; cc++) {
            kv[cc] = kss[c0 + cc];
            if (msk[c0 + cc]) mb |= 1u << cc;
        }

        #pragma unroll
        for (int u = 0; u < 4; u++) {
            const float qv = qss[qr + (u << 6)];
            float p[16];
            float tmax = -1e30f;
            #pragma unroll
            for (int cc = 0; cc < 16; cc++) {
                const float sv = ((mb >> cc) & 1u) ? -1000.0f : qv * kv[cc];
                p[cc] = sv;
                tmax = fmaxf(tmax, sv);
            }
            tmax = fmaxf(tmax, __shfl_xor_sync(0xffffffffu, tmax, 1));
            tmax = fmaxf(tmax, __shfl_xor_sync(0xffffffffu, tmax, 2));
            const float m_new = fmaxf(m_run[u], tmax);

            float psum = 0.f;
            #pragma unroll
            for (int cc = 0; cc < 16; cc++) {
                const float e = __expf(p[cc] - m_new);
                p[cc] = e;
                psum += e;
            }
            float* prow = &Ps[(qr + (u << 6)) * 68 + c0];
            #pragma unroll
            for (int j = 0; j < 16; j += 4)
                *(float4*)(prow + j) = make_float4(p[j], p[j + 1], p[j + 2], p[j + 3]);

            psum += __shfl_xor_sync(0xffffffffu, psum, 1);
            psum += __shfl_xor_sync(0xffffffffu, psum, 2);

            const float scale = __expf(m_run[u] - m_new);
            l_run[u] = l_run[u] * scale + psum;
            m_run[u] = m_new;
            const ull sc2 = pack2(scale, scale);
            #pragma unroll
            for (int j = 0; j < 8; j++) mul2(acc[u][j], sc2);
        }
        __syncthreads();   // Ps complete

        #pragma unroll 2
        for (int n = 0; n < 64; n++) {
            const ulonglong2* vrow = (const ulonglong2*)&Vs[n * 68 + c0];
            const ulonglong2 va = vrow[0], vb = vrow[1], vc = vrow[2], vd = vrow[3];
            #pragma unroll
            for (int u = 0; u < 4; u++) {
                const float pv = Ps[(qr + (u << 6)) * 68 + n];
                const ull pd = pack2(pv, pv);
                fma2(acc[u][0], pd, va.x); fma2(acc[u][1], pd, va.y);
                fma2(acc[u][2], pd, vb.x); fma2(acc[u][3], pd, vb.y);
                fma2(acc[u][4], pd, vc.x); fma2(acc[u][5], pd, vc.y);
                fma2(acc[u][6], pd, vd.x); fma2(acc[u][7], pd, vd.y);
            }
        }
    }

    // chunked + tf32-rounded output. TOKEN row = (seq_pos)*BATCH + b  (x is [M,B,D]).
    #pragma unroll
    for (int u = 0; u < 4; u++) {
        const float inv = 1.f / l_run[u];
        const int row = (m0 + qr + (u << 6)) * BATCH + b;   // FIXED: token-row mapping
        const int rw7 = row & 7;
        #pragma unroll
        for (int j = 0; j < 4; j++) {
            const float2 pa = unpack2(acc[u][2 * j]);
            const float2 pb = unpack2(acc[u][2 * j + 1]);
            float4 ov;
            ov.x = tf32f(pa.x * inv); ov.y = tf32f(pa.y * inv);
            ov.z = tf32f(pb.x * inv); ov.w = tf32f(pb.y * inv);
            const int col = h * 64 + c0 + (j << 2);
            const size_t oidx = ((size_t)(col >> 5) * M_TOK + row) * 32 +
                                ((((col >> 2) & 7) ^ rw7) << 2);
            *(float4*)(pool + oidx) = ov;
        }
    }
}

// ---------------- launcher ----------------
extern "C" void kernel_launch(void* const* d_in, const int* in_sizes, int n_in,
                              void* d_out, int out_size)
{
    const float* x     = (const float*)d_in[0];
    const unsigned char* mask = (const unsigned char*)d_in[1];
    const float* ln1_g = (const float*)d_in[2];
    const float* ln1_b = (const float*)d_in[3];
    const float* wq    = (const float*)d_in[4];
    const float* bq    = (const float*)d_in[5];
    const float* wk    = (const float*)d_in[6];
    const float* bk    = (const float*)d_in[7];
    const float* wv    = (const float*)d_in[8];
    const float* bv    = (const float*)d_in[9];
    const float* wo    = (const float*)d_in[10];
    const float* bo    = (const float*)d_in[11];
    const float* ln2_g = (const float*)d_in[12];
    const float* ln2_b = (const float*)d_in[13];
    const float* w1    = (const float*)d_in[14];
    const float* b1    = (const float*)d_in[15];
    const float* w2    = (const float*)d_in[16];
    const float* b2    = (const float*)d_in[17];
    float* out = (float*)d_out;

    float* scratch = nullptr;
    cudaGetSymbolAddress((void**)&scratch, g_scratch);
    float* xn   = scratch + OFF_XN;
    float* vbuf = scratch + OFF_V;
    float* pool = scratch + OFF_POOL;
    float* x2   = scratch + OFF_X2;
    float* hbuf = scratch + OFF_H;
    float* qsb  = scratch + OFF_QS;
    float* ksb  = scratch + OFF_KS;
    float* wqk  = scratch + OFF_WQK;
    float* bqk  = scratch + OFF_BQK;
    float* wvt  = scratch + OFF_WVT;
    float* wot  = scratch + OFF_WOT;
    float* w1t  = scratch + OFF_W1T;
    float* w2t  = scratch + OFF_W2T;

    cudaFuncSetAttribute(sgemm_tc<false, false, false>, cudaFuncAttributeMaxDynamicSharedMemorySize, TC_SMEM_TOTAL);
    cudaFuncSetAttribute(sgemm_tc<false, true,  false>, cudaFuncAttributeMaxDynamicSharedMemorySize, TC_SMEM_TOTAL);
    cudaFuncSetAttribute(sgemm_tc<true,  false, true >, cudaFuncAttributeMaxDynamicSharedMemorySize, TC_SMEM_TOTAL);
    cudaFuncSetAttribute(attn_kernel, cudaFuncAttributeMaxDynamicSharedMemorySize,
                         ATTN_SMEM_FLOATS * 4);

    // weight transposes into chunked+rounded layout
    transpose_kernel<<<dim3(32, 32),  256>>>(wv, wvt, D_MODEL, D_MODEL);
    transpose_kernel<<<dim3(32, 32),  256>>>(wo, wot, D_MODEL, D_MODEL);
    transpose_kernel<<<dim3(128, 32), 256>>>(w1, w1t, D_MODEL, FF_DIM);
    transpose_kernel<<<dim3(32, 128), 256>>>(w2, w2t, FF_DIM, D_MODEL);

    // 1. xn = LN1(x)  (chunked, tf32-rounded)
    ln_kernel<<<M_TOK, 256>>>(x, ln1_g, ln1_b, xn);
    // 2. fold head-sums of wq/wk (rank-1 attention)
    headsum_kernel<<<64, 256>>>(wq, bq, wk, bk, wqk, bqk);
    // 3. v = xn @ wv + bv   (tcgen05, row-major fp32 out)
    sgemm_tc<false, false, false><<<dim3(D_MODEL / 256, M_TOK / 256), 256, TC_SMEM_TOTAL>>>(
        xn, wvt, bv, nullptr, vbuf, D_MODEL, D_MODEL);
    // 4. qs/ks = xn @ wqk + bqk
    qsks_gemm<<<M_TOK / 128, 256>>>(xn, wqk, bqk, qsb, ksb);
    // 5. pooled = softmax(qs ⊗ ks, masked) @ v   (chunked+rounded out)
    attn_kernel<<<dim3(SEQ / 256, BATCH * NHEAD), 256, ATTN_SMEM_FLOATS * 4>>>(
        qsb, ksb, vbuf, mask, pool);
    // 6. x2 = pooled @ wo + bo + x   (row-major fp32 out)
    sgemm_tc<false, true, false><<<dim3(D_MODEL / 256, M_TOK / 256), 256, TC_SMEM_TOTAL>>>(
        pool, wot, bo, x, x2, D_MODEL, D_MODEL);
    // 7. xn = LN2(x2)  (chunked, rounded)
    ln_kernel<<<M_TOK, 256>>>(x2, ln2_g, ln2_b, xn);
    // 8. h = relu(xn @ w1 + b1)   (chunked+rounded out)
    sgemm_tc<true, false, true><<<dim3(FF_DIM / 256, M_TOK / 256), 256, TC_SMEM_TOTAL>>>(
        xn, w1t, b1, nullptr, hbuf, FF_DIM, D_MODEL);
    // 9. out = h @ w2 + b2 + x2   (row-major fp32 out)
    sgemm_tc<false, true, false><<<dim3(D_MODEL / 256, M_TOK / 256), 256, TC_SMEM_TOTAL>>>(
        hbuf, w2t, b2, x2, out, D_MODEL, FF_DIM);
}

// round 8
// speedup vs baseline: 16.0609x; 1.8454x over previous
#include <cuda_runtime.h>
#include <cstddef>
#include <cstdint>

// Problem constants
#define M_TOK   8192     // M*B token rows
#define D_MODEL 1024
#define FF_DIM  4096
#define NHEAD   16
#define DHEAD   64
#define SEQ     1024
#define BATCH   8

// tcgen05 is arch-SPECIFIC (sm_103a). nvcc also runs a generic compute_103 PTX
// pass where these instructions don't exist — compile a stub there.
#if defined(__CUDA_ARCH__) && (defined(__CUDA_ARCH_FEAT_SM103_ALL) || defined(__CUDA_ARCH_SPECIFIC__))
#define HAS_TCGEN05 1
#else
#define HAS_TCGEN05 0
#endif

typedef unsigned long long ull;

// ---------------- tcgen05 / TMA helpers ----------------
static constexpr uint64_t SMEM_DESC_BASE_SW128 =
    (uint64_t(2)  << 61) | (uint64_t(1) << 46) | (uint64_t(64) << 32) | (uint64_t(1) << 16);
#define MAKE_SMEM_DESC(base_addr) \
    (SMEM_DESC_BASE_SW128 | ((uint64_t)((base_addr) >> 4) & 0x3FFF))

__device__ __forceinline__ uint32_t smem_to_u32(const void* p) {
    uint32_t a;
    asm("{ .reg .u64 t; cvta.to.shared.u64 t, %1; cvt.u32.u64 %0, t; }" : "=r"(a) : "l"(p));
    return a;
}
__device__ __forceinline__ uint32_t tf32_of(float f) {
    uint32_t r; asm("cvt.rna.tf32.f32 %0, %1;" : "=r"(r) : "f"(f)); return r;
}
__device__ __forceinline__ float tf32f(float f) {
    return __uint_as_float(tf32_of(f));
}

#if HAS_TCGEN05
#define TCGEN05_ALLOC(smem_res, nCols) \
    asm volatile("tcgen05.alloc.cta_group::1.sync.aligned.shared::cta.b32 [%0], %1;" \
                 :: "r"((uint32_t)(smem_res)), "r"((uint32_t)(nCols)) : "memory")
#define TCGEN05_DEALLOC(tmem, nCols) \
    asm volatile("tcgen05.dealloc.cta_group::1.sync.aligned.b32 %0, %1;" \
                 :: "r"(tmem), "r"((uint32_t)(nCols)))
#define TCGEN05_RELINQUISH() \
    asm volatile("tcgen05.relinquish_alloc_permit.cta_group::1.sync.aligned;")
#define TCGEN05_WAIT_LD() asm volatile("tcgen05.wait::ld.sync.aligned;" ::: "memory")
#define TC_FENCE_AFTER()  asm volatile("tcgen05.fence::after_thread_sync;" ::: "memory")
#define TC_COMMIT(mbar) \
    asm volatile("tcgen05.commit.cta_group::1.mbarrier::arrive::one.shared::cluster.b64 [%0];" \
                 :: "r"((uint32_t)(mbar)) : "memory")
#endif

#define FENCE_PROXY_ASYNC() asm volatile("fence.proxy.async.shared::cta;" ::: "memory")
#define MBARRIER_INIT(mbar, cnt) \
    asm volatile("mbarrier.init.shared.b64 [%0], %1;" :: "r"((uint32_t)(mbar)), "r"((uint32_t)(cnt)) : "memory")
#define MBARRIER_EXPECT_TX(mbar, bytes) \
    asm volatile("mbarrier.arrive.expect_tx.shared.b64 _, [%0], %1;" \
                 :: "r"((uint32_t)(mbar)), "r"((uint32_t)(bytes)) : "memory")
#define MBAR_WAIT(mbar, ph) \
    asm volatile("{\n\t.reg .pred P;\n\tWL%=:\n\t" \
                 "mbarrier.try_wait.parity.acquire.cta.shared::cta.b64 P, [%0], %1, 0x989680;\n\t" \
                 "@!P bra WL%=;\n\t}" :: "r"((uint32_t)(mbar)), "r"((uint32_t)(ph)) : "memory")
#define BULK_G2S(dst, src, bytes, mbar) \
    asm volatile("cp.async.bulk.shared::cta.global.mbarrier::complete_tx::bytes [%0], [%1], %2, [%3];" \
                 :: "r"((uint32_t)(dst)), "l"(src), "r"((uint32_t)(bytes)), "r"((uint32_t)(mbar)) : "memory")

#if HAS_TCGEN05
#define TCGEN05_LD_32X32B_X32(r, tmem_addr) \
    asm volatile( \
        "tcgen05.ld.sync.aligned.32x32b.x32.b32 " \
        "{%0, %1, %2, %3, %4, %5, %6, %7, " \
        " %8, %9, %10, %11, %12, %13, %14, %15, " \
        " %16, %17, %18, %19, %20, %21, %22, %23, " \
        " %24, %25, %26, %27, %28, %29, %30, %31}, [%32];" \
        : "=r"((r)[0]),  "=r"((r)[1]),  "=r"((r)[2]),  "=r"((r)[3]), \
          "=r"((r)[4]),  "=r"((r)[5]),  "=r"((r)[6]),  "=r"((r)[7]), \
          "=r"((r)[8]),  "=r"((r)[9]),  "=r"((r)[10]), "=r"((r)[11]), \
          "=r"((r)[12]), "=r"((r)[13]), "=r"((r)[14]), "=r"((r)[15]), \
          "=r"((r)[16]), "=r"((r)[17]), "=r"((r)[18]), "=r"((r)[19]), \
          "=r"((r)[20]), "=r"((r)[21]), "=r"((r)[22]), "=r"((r)[23]), \
          "=r"((r)[24]), "=r"((r)[25]), "=r"((r)[26]), "=r"((r)[27]), \
          "=r"((r)[28]), "=r"((r)[29]), "=r"((r)[30]), "=r"((r)[31]) \
        : "r"(tmem_addr))

// tf32 SS MMA, cg1. idesc: dfmt F32(1<<4) | a TF32(2<<7) | b TF32(2<<10) | (N/8)<<17 | (M/16)<<24
__device__ __forceinline__ void mma_tf32_ss(uint32_t d_tmem, uint64_t a_desc, uint64_t b_desc,
                                            uint32_t idesc, uint32_t en)
{
    asm volatile(
        "{\n\t"
        ".reg .pred p;\n\t"
        "setp.ne.u32 p, %5, 0;\n\t"
        "tcgen05.mma.cta_group::1.kind::tf32 [%0], %1, %2, %3, {%4, %4, %4, %4}, p;\n\t"
        "}"
        :: "r"(d_tmem), "l"(a_desc), "l"(b_desc), "r"(idesc), "r"(0u), "r"(en)
        : "memory");
}
#endif

// ================= chunked + pre-swizzled GEMM operand layout =================
// element (row, k) of an operand with R total rows lives at float index:
//   ((k>>5)*R + row)*32 + (((k>>2)&7) ^ (row&7))*4 + (k&3)
__device__ __forceinline__ size_t chunk_idx(int row, int k, int R) {
    return ((size_t)(k >> 5) * R + row) * 32 + ((((k >> 2) & 7) ^ (row & 7)) << 2) + (k & 3);
}

// ---------------- scratch (static device memory) ----------------
static const size_t OFF_XN    = 0;
static const size_t OFF_V     = 8388608;
static const size_t OFF_POOL  = 16777216;
static const size_t OFF_X2    = 25165824;
static const size_t OFF_H     = 33554432;
static const size_t OFF_QS    = 67108864;
static const size_t OFF_KS    = 67239936;
static const size_t OFF_WQK   = 67371008;   // [1024][32]
static const size_t OFF_BQK   = 67403776;   // [32]
static const size_t OFF_WVT   = 67403808;   // chunked
static const size_t OFF_WOT   = 68452384;
static const size_t OFF_W1T   = 69500960;
static const size_t OFF_W2T   = 73695264;
static const size_t OFF_KSTAT = 77889568;   // float4[128] = 512 floats
static const size_t SCRATCH_FLOATS = 77890080;

__device__ float g_scratch[SCRATCH_FLOATS];

// ---------------- LayerNorm: row-major in -> chunked tf32-rounded out --------
__global__ void __launch_bounds__(256)
ln_kernel(const float* __restrict__ x, const float* __restrict__ g,
          const float* __restrict__ bta, float* __restrict__ y)
{
    const int row = blockIdx.x;
    const int tx  = threadIdx.x;
    const float4 v = ((const float4*)(x + (size_t)row * D_MODEL))[tx];

    float s  = v.x + v.y + v.z + v.w;
    float sq = v.x * v.x + v.y * v.y + v.z * v.z + v.w * v.w;
    #pragma unroll
    for (int o = 16; o; o >>= 1) {
        s  += __shfl_xor_sync(0xffffffffu, s,  o);
        sq += __shfl_xor_sync(0xffffffffu, sq, o);
    }
    __shared__ float ss[8], ssq[8];
    const int w = tx >> 5, l = tx & 31;
    if (l == 0) { ss[w] = s; ssq[w] = sq; }
    __syncthreads();
    s = 0.f; sq = 0.f;
    #pragma unroll
    for (int i = 0; i < 8; i++) { s += ss[i]; sq += ssq[i]; }

    const float mean = s * (1.f / D_MODEL);
    const float var  = sq * (1.f / D_MODEL) - mean * mean;
    const float rstd = rsqrtf(var + 1e-5f);

    const float4 gv = ((const float4*)g)[tx];
    const float4 bv = ((const float4*)bta)[tx];
    float4 o4;
    o4.x = tf32f((v.x - mean) * rstd * gv.x + bv.x);
    o4.y = tf32f((v.y - mean) * rstd * gv.y + bv.y);
    o4.z = tf32f((v.z - mean) * rstd * gv.z + bv.z);
    o4.w = tf32f((v.w - mean) * rstd * gv.w + bv.w);
    const size_t oidx = ((size_t)(tx >> 3) * M_TOK + row) * 32 + (((tx & 7) ^ (row & 7)) << 2);
    *(float4*)(y + oidx) = o4;
}

// ---------------- transpose into chunked layout: in[K][N] -> outT(n,k) -------
__global__ void __launch_bounds__(256)
transpose_kernel(const float* __restrict__ in, float* __restrict__ out, int K, int N)
{
    __shared__ float t[32][33];
    const int k0 = blockIdx.y << 5;
    const int n0 = blockIdx.x << 5;
    const int tx = threadIdx.x & 31;
    const int ty = threadIdx.x >> 5;   // 0..7
    #pragma unroll
    for (int i = 0; i < 4; i++)
        t[ty + (i << 3)][tx] = in[(size_t)(k0 + ty + (i << 3)) * N + n0 + tx];
    __syncthreads();
    #pragma unroll
    for (int i = 0; i < 4; i++) {
        const int n = n0 + ty + (i << 3);
        const int k = k0 + tx;
        out[chunk_idx(n, k, N)] = tf32f(t[tx][ty + (i << 3)]);
    }
}

// ---------------- head-sum of wq/wk columns into combined [1024][32] ---------
__global__ void headsum_kernel(const float* __restrict__ wq, const float* __restrict__ bq,
                               const float* __restrict__ wk, const float* __restrict__ bk,
                               float* __restrict__ wqk, float* __restrict__ bqk)
{
    const int idx = blockIdx.x * blockDim.x + threadIdx.x;
    if (idx < D_MODEL * NHEAD) {
        const int d = idx >> 4, h = idx & 15;
        const float* pq = wq + (size_t)d * D_MODEL + h * DHEAD;
        const float* pk = wk + (size_t)d * D_MODEL + h * DHEAD;
        float sq = 0.f, sk = 0.f;
        #pragma unroll 8
        for (int i = 0; i < DHEAD; i++) { sq += pq[i]; sk += pk[i]; }
        wqk[d * 32 + h]      = sq;
        wqk[d * 32 + 16 + h] = sk;
    }
    if (idx < NHEAD) {
        float sq = 0.f, sk = 0.f;
        for (int i = 0; i < DHEAD; i++) {
            sq += bq[idx * DHEAD + i];
            sk += bk[idx * DHEAD + i];
        }
        bqk[idx] = sq; bqk[16 + idx] = sk;
    }
}

// ---------------- skinny GEMM v2: C[8192,32] = xn(chunked) @ wqk + bqk → qs|ks
// 128 blocks x 64 rows; thread = (row, 8-col group); A row chunk in registers.
__global__ void __launch_bounds__(256)
qsks_gemm(const float* __restrict__ xn, const float* __restrict__ wqk,
          const float* __restrict__ bqk, float* __restrict__ qs, float* __restrict__ ks)
{
    __shared__ float Araw[2048];      // one 8KB chunk for 64 rows, swizzled layout
    __shared__ float Wsm[32][36];

    const int tx = threadIdx.x;
    const int r  = tx >> 2;           // 0..63
    const int cg = tx & 3;            // col group: cols cg*8..cg*8+7
    const int brow = blockIdx.x << 6;
    const int p7 = r & 7;             // (brow+r)&7 == r&7 since brow % 64 == 0

    float acc[8];
    #pragma unroll
    for (int j = 0; j < 8; j++) acc[j] = 0.f;

    for (int chk = 0; chk < 32; chk++) {
        const float4* src = (const float4*)(xn + ((size_t)chk * M_TOK + brow) * 32);
        ((float4*)Araw)[tx]       = src[tx];
        ((float4*)Araw)[tx + 256] = src[tx + 256];
        {
            const int row = tx >> 3, c4 = (tx & 7) << 2;
            *(float4*)&Wsm[row][c4] = *(const float4*)(wqk + (size_t)(chk * 32 + row) * 32 + c4);
        }
        __syncthreads();

        float4 a4[8];
        #pragma unroll
        for (int j = 0; j < 8; j++)
            a4[j] = *(const float4*)&Araw[r * 32 + ((j ^ p7) << 2)];

        #pragma unroll
        for (int kk = 0; kk < 32; kk++) {
            const float a = ((const float*)&a4[kk >> 2])[kk & 3];
            const float4 w0 = *(const float4*)&Wsm[kk][cg * 8];
            const float4 w1 = *(const float4*)&Wsm[kk][cg * 8 + 4];
            acc[0] = fmaf(a, w0.x, acc[0]); acc[1] = fmaf(a, w0.y, acc[1]);
            acc[2] = fmaf(a, w0.z, acc[2]); acc[3] = fmaf(a, w0.w, acc[3]);
            acc[4] = fmaf(a, w1.x, acc[4]); acc[5] = fmaf(a, w1.y, acc[5]);
            acc[6] = fmaf(a, w1.z, acc[6]); acc[7] = fmaf(a, w1.w, acc[7]);
        }
        __syncthreads();
    }

    const size_t row = (size_t)(brow + r);
    #pragma unroll
    for (int j = 0; j < 8; j++) {
        const int c = cg * 8 + j;
        const float v = acc[j] + bqk[c];
        if (c < 16) qs[row * NHEAD + c]        = v;
        else        ks[row * NHEAD + (c - 16)] = v;
    }
}

// ---------------- per-(b,h) key stats: kmax/kmin over unmasked, anyMasked ----
__global__ void __launch_bounds__(256)
kminmax_kernel(const float* __restrict__ ks, const unsigned char* __restrict__ mask,
               float4* __restrict__ kstat)
{
    const int bh = blockIdx.x;
    const int b  = bh >> 4;
    const int h  = bh & 15;
    const int tx = threadIdx.x;

    float kmx = -1e30f, kmn = 1e30f;
    int cnt = 0, anym = 0;
    for (int n = tx; n < SEQ; n += 256) {
        const float kv = ks[((size_t)n * BATCH + b) * NHEAD + h];
        if (mask[(size_t)n * BATCH + b]) anym = 1;
        else { kmx = fmaxf(kmx, kv); kmn = fminf(kmn, kv); cnt++; }
    }
    __shared__ float smx[256], smn[256];
    __shared__ int scnt[256], sany[256];
    smx[tx] = kmx; smn[tx] = kmn; scnt[tx] = cnt; sany[tx] = anym;
    __syncthreads();
    for (int o = 128; o; o >>= 1) {
        if (tx < o) {
            smx[tx] = fmaxf(smx[tx], smx[tx + o]);
            smn[tx] = fminf(smn[tx], smn[tx + o]);
            scnt[tx] += scnt[tx + o];
            sany[tx] |= sany[tx + o];
        }
        __syncthreads();
    }
    if (tx == 0)
        kstat[bh] = make_float4(smx[0], smn[0], sany[0] ? 1.f : 0.f, (float)scnt[0]);
}

// ======== tcgen05 tf32 GEMM: 256x256 supertile, 3-stage cp.async.bulk pipeline ========
#define TC_STAGES   3
#define TC_HDR      1024
#define TC_STAGE_SZ 65536
#define TC_SMEM_TOTAL (TC_HDR + TC_STAGES * TC_STAGE_SZ)   // 197632
#define TC_IDESC  ((1u << 4) | (2u << 7) | (2u << 10) | (32u << 17) | (8u << 24))  // N=256, M=128

template<bool RELU, bool RESID, bool CHUNKOUT, bool TF32ROUND>
__global__ void __launch_bounds__(256)
sgemm_tc(const float* __restrict__ A, const float* __restrict__ Wt,
         const float* __restrict__ bias, const float* __restrict__ resid,
         float* __restrict__ C, int N, int K)
{
#if HAS_TCGEN05
    extern __shared__ char sm[];
    const uint32_t sb = smem_to_u32(sm);
    const int tx = threadIdx.x;
    const int brow = blockIdx.y << 8;   // 256 M rows
    const int bcol = blockIdx.x << 8;   // 256 N cols

    if ((tx >> 5) == 0) TCGEN05_ALLOC(sb, 512);
    if (tx == 0) {
        #pragma unroll
        for (int s = 0; s < TC_STAGES; s++) {
            MBARRIER_INIT(sb + 8 + s * 8, 1);    // full[s]
            MBARRIER_INIT(sb + 32 + s * 8, 1);   // done[s]
        }
    }
    __syncthreads();
    if ((tx >> 5) == 0) TCGEN05_RELINQUISH();
    uint32_t tmem;
    asm volatile("ld.shared.b32 %0, [%1];" : "=r"(tmem) : "r"(sb));

    const int nchunk = K >> 5;

    if (tx == 0) {
        TC_FENCE_AFTER();
        #pragma unroll
        for (int i = 0; i < TC_STAGES; i++) {
            const int s = i;
            const uint32_t full = sb + 8 + s * 8;
            MBARRIER_EXPECT_TX(full, 2 * 32768);
            BULK_G2S(sb + TC_HDR + s * TC_STAGE_SZ,
                     A + ((size_t)i * M_TOK + brow) * 32, 32768, full);
            BULK_G2S(sb + TC_HDR + s * TC_STAGE_SZ + 32768,
                     Wt + ((size_t)i * N + bcol) * 32, 32768, full);
        }
        for (int i = 0; i < nchunk; i++) {
            const int s = i % TC_STAGES;
            const int ph = (i / TC_STAGES) & 1;
            MBAR_WAIT(sb + 8 + s * 8, ph);
            const uint32_t abase = sb + TC_HDR + s * TC_STAGE_SZ;
            const uint64_t ad0 = MAKE_SMEM_DESC(abase);
            const uint64_t ad1 = MAKE_SMEM_DESC(abase + 16384);
            const uint64_t bd  = MAKE_SMEM_DESC(abase + 32768);
            #pragma unroll
            for (int k8 = 0; k8 < 4; k8++) {
                const uint32_t en = (i | k8) ? 1u : 0u;
                mma_tf32_ss(tmem,       ad0 + 2 * k8, bd + 2 * k8, TC_IDESC, en);
                mma_tf32_ss(tmem + 256, ad1 + 2 * k8, bd + 2 * k8, TC_IDESC, en);
            }
            TC_COMMIT(sb + 32 + s * 8);
            const int j = i + TC_STAGES;
            if (j < nchunk) {
                MBAR_WAIT(sb + 32 + s * 8, ph);
                const uint32_t full = sb + 8 + s * 8;
                MBARRIER_EXPECT_TX(full, 2 * 32768);
                BULK_G2S(abase,         A + ((size_t)j * M_TOK + brow) * 32, 32768, full);
                BULK_G2S(abase + 32768, Wt + ((size_t)j * N + bcol) * 32, 32768, full);
            }
        }
        for (int j = nchunk - TC_STAGES; j < nchunk; j++) {
            const int s = j % TC_STAGES;
            MBAR_WAIT(sb + 32 + s * 8, (j / TC_STAGES) & 1);
        }
    }
    __syncthreads();
    TC_FENCE_AFTER();

    {
        const int w     = tx >> 5;
        const int lane  = tx & 31;
        const int mtile = w >> 2;
        const int row   = brow + (mtile << 7) + ((w & 3) << 5) + lane;
        const int rw7   = row & 7;
        #pragma unroll
        for (int slab = 0; slab < 4; slab++) {
            uint32_t d[64];
            TCGEN05_LD_32X32B_X32(d,      tmem + mtile * 256 + slab * 64);
            TCGEN05_LD_32X32B_X32(d + 32, tmem + mtile * 256 + slab * 64 + 32);
            TCGEN05_WAIT_LD();
            const int cb = bcol + slab * 64;
            const float* bp = bias + cb;
            const float* rp = RESID ? (resid + (size_t)row * N + cb) : nullptr;
            #pragma unroll
            for (int j = 0; j < 64; j += 4) {
                const float4 bv = *(const float4*)(bp + j);
                float4 o;
                o.x = __uint_as_float(d[j + 0]) + bv.x;
                o.y = __uint_as_float(d[j + 1]) + bv.y;
                o.z = __uint_as_float(d[j + 2]) + bv.z;
                o.w = __uint_as_float(d[j + 3]) + bv.w;
                if (RESID) {
                    const float4 rv = *(const float4*)(rp + j);
                    o.x += rv.x; o.y += rv.y; o.z += rv.z; o.w += rv.w;
                }
                if (RELU) {
                    o.x = fmaxf(o.x, 0.f); o.y = fmaxf(o.y, 0.f);
                    o.z = fmaxf(o.z, 0.f); o.w = fmaxf(o.w, 0.f);
                }
                if (CHUNKOUT) {
                    const int col = cb + j;
                    float4 q;
                    q.x = tf32f(o.x); q.y = tf32f(o.y); q.z = tf32f(o.z); q.w = tf32f(o.w);
                    const size_t oidx = ((size_t)(col >> 5) * M_TOK + row) * 32 +
                                        ((((col >> 2) & 7) ^ rw7) << 2);
                    *(float4*)(C + oidx) = q;
                } else {
                    float4 q = o;
                    if (TF32ROUND) {
                        q.x = tf32f(o.x); q.y = tf32f(o.y);
                        q.z = tf32f(o.z); q.w = tf32f(o.w);
                    }
                    *(float4*)(C + (size_t)row * N + cb + j) = q;
                }
            }
        }
    }

    __syncthreads();
    if ((tx >> 5) == 0) TCGEN05_DEALLOC(tmem, 512);
#endif // HAS_TCGEN05
}

// ================= tensor-core attention ======================================
// Rank-1 scores: pot[m,n] = qs_m * ks_n (masked -> -1000). Softmax max is
// closed-form: m_q = max(q*kmax, q*kmin) (unmasked), max'd with -1000 if any
// masked. So no online rescaling: P tiles (tf32, swizzled) accumulate into a
// TMEM D = P@V^T across all key tiles; epilogue divides by l.
// Block: 128 queries x one (b,h). 16 key tiles of 64. Double-buffered P+Vt.
//
// smem layout (bytes): 0 tmemptr | 8,16 done mbars | 64 lsum[256] | 1088 ksm[64]
//                      | 1344 mbits[2] | 2048 P0 (32KB) | 34816 P1 | 67584 V0 (16KB) | 83968 V1
#define AT_SMEM_TOTAL 100352
#define AT_P(s)   (2048 + (s) * 32768)
#define AT_V(s)   (67584 + (s) * 16384)
#define AT_IDESC  ((1u << 4) | (2u << 7) | (2u << 10) | (8u << 17) | (8u << 24))  // N=64, M=128

__global__ void __launch_bounds__(256)
attn_kernel(const float* __restrict__ qs, const float* __restrict__ ks,
            const float* __restrict__ v, const unsigned char* __restrict__ mask,
            const float4* __restrict__ kstat, float* __restrict__ pool)
{
#if HAS_TCGEN05
    extern __shared__ char sm[];
    const uint32_t sb = smem_to_u32(sm);
    float* lsum = (float*)(sm + 64);
    float* ksm  = (float*)(sm + 1088);
    unsigned* mbits = (unsigned*)(sm + 1344);

    const int tx = threadIdx.x;
    const int bh = blockIdx.y;
    const int b  = bh >> 4;
    const int h  = bh & 15;
    const int m0 = blockIdx.x << 7;     // 128 queries

    const int q     = tx & 127;
    const int nhalf = tx >> 7;          // 0/1 -> n' in [32*nhalf, 32*nhalf+32)
    const int q7    = q & 7;

    if ((tx >> 5) == 0) TCGEN05_ALLOC(sb, 64);
    if (tx == 0) { MBARRIER_INIT(sb + 8, 1); MBARRIER_INIT(sb + 16, 1); }
    __syncthreads();
    if ((tx >> 5) == 0) TCGEN05_RELINQUISH();
    uint32_t tmem;
    asm volatile("ld.shared.b32 %0, [%1];" : "=r"(tmem) : "r"(sb));

    // per-thread query scalar + closed-form softmax max
    const float qv = qs[((size_t)(m0 + q) * BATCH + b) * NHEAD + h];
    const float4 kst = kstat[bh];
    float mu = (kst.w > 0.f) ? fmaxf(qv * kst.x, qv * kst.y) : -1e30f;
    const float mq = (kst.z > 0.f) ? fmaxf(mu, -1000.0f) : mu;

    float lpart = 0.f;
    int dph0 = 0, dph1 = 0;

    // V load/transpose role: n-row and d-quad
    const int vn = tx >> 2;             // 0..63
    const int dq = (tx & 3) << 4;       // 0,16,32,48

    for (int i = 0; i < 16; i++) {
        const int s  = i & 1;
        const int n0 = i << 6;
        if (i >= 2) {
            if (s == 0) { MBAR_WAIT(sb + 8,  dph0); dph0 ^= 1; }
            else        { MBAR_WAIT(sb + 16, dph1); dph1 ^= 1; }
        }

        // ks + mask bits (warps 0,1)
        if (tx < 64) {
            ksm[tx] = ks[((size_t)(n0 + tx) * BATCH + b) * NHEAD + h];
            const bool mm = mask[(size_t)(n0 + tx) * BATCH + b] != 0;
            const unsigned bal = __ballot_sync(0xffffffffu, mm);
            if ((tx & 31) == 0) mbits[tx >> 5] = bal;
        }

        // V tile load + transpose into Vt[s] (swizzled chunked [64 d][32 n] x2)
        {
            const float4* vp = (const float4*)(v + ((size_t)(n0 + vn) * BATCH + b) * D_MODEL
                                                 + h * DHEAD + dq);
            const float4 va0 = vp[0], va1 = vp[1], va2 = vp[2], va3 = vp[3];
            const float vals[16] = {va0.x, va0.y, va0.z, va0.w, va1.x, va1.y, va1.z, va1.w,
                                    va2.x, va2.y, va2.z, va2.w, va3.x, va3.y, va3.z, va3.w};
            char* vtb = sm + AT_V(s) + (vn >> 5) * 8192;
            const int np = (vn >> 2) & 7;
            const int nl = (vn & 3) << 2;
            #pragma unroll
            for (int e = 0; e < 16; e++) {
                const int d = dq + e;
                *(float*)(vtb + d * 128 + ((np ^ (d & 7)) << 4) + nl) = vals[e];
            }
        }
        __syncthreads();   // ksm/mbits visible

        // P compute: 32 exps per thread -> swizzled STS into P[s]
        {
            const unsigned mb = mbits[nhalf];
            char* pb = sm + AT_P(s) + nhalf * 16384 + q * 128;
            #pragma unroll
            for (int g = 0; g < 8; g++) {
                float4 pf;
                float pe[4];
                #pragma unroll
                for (int e = 0; e < 4; e++) {
                    const int np_ = g * 4 + e;
                    const float kv = ksm[nhalf * 32 + np_];
                    const float sc = ((mb >> np_) & 1u) ? -1000.0f : qv * kv;
                    pe[e] = tf32f(__expf(sc - mq));
                    lpart += pe[e];
                }
                pf.x = pe[0]; pf.y = pe[1]; pf.z = pe[2]; pf.w = pe[3];
                *(float4*)(pb + ((g ^ q7) << 4)) = pf;
            }
        }
        FENCE_PROXY_ASYNC();
        __syncthreads();   // P + Vt complete

        if (tx == 0) {
            TC_FENCE_AFTER();
            const uint64_t pd0 = MAKE_SMEM_DESC(sb + AT_P(s));
            const uint64_t pd1 = MAKE_SMEM_DESC(sb + AT_P(s) + 16384);
            const uint64_t vd0 = MAKE_SMEM_DESC(sb + AT_V(s));
            const uint64_t vd1 = MAKE_SMEM_DESC(sb + AT_V(s) + 8192);
            #pragma unroll
            for (int k8 = 0; k8 < 4; k8++)
                mma_tf32_ss(tmem, pd0 + 2 * k8, vd0 + 2 * k8, AT_IDESC, (i | k8) ? 1u : 0u);
            #pragma unroll
            for (int k8 = 0; k8 < 4; k8++)
                mma_tf32_ss(tmem, pd1 + 2 * k8, vd1 + 2 * k8, AT_IDESC, 1u);
            TC_COMMIT(sb + 8 + s * 8);
        }
    }

    MBAR_WAIT(sb + 8,  dph0);
    MBAR_WAIT(sb + 16, dph1);
    lsum[tx] = lpart;
    __syncthreads();
    TC_FENCE_AFTER();

    // epilogue: warps 0..3 read D[128][64] from TMEM, scale by 1/l, chunked out
    const int w = tx >> 5;
    if (w < 4) {
        const int lane = tx & 31;
        const int ql   = w * 32 + lane;
        uint32_t d[64];
        TCGEN05_LD_32X32B_X32(d,      tmem);
        TCGEN05_LD_32X32B_X32(d + 32, tmem + 32);
        TCGEN05_WAIT_LD();

        const float inv = 1.f / (lsum[ql] + lsum[ql + 128]);
        const int row = (m0 + ql) * BATCH + b;
        const int rw7 = row & 7;
        #pragma unroll
        for (int jg = 0; jg < 16; jg++) {
            const int col = h * 64 + jg * 4;
            float4 o;
            o.x = tf32f(__uint_as_float(d[jg * 4 + 0]) * inv);
            o.y = tf32f(__uint_as_float(d[jg * 4 + 1]) * inv);
            o.z = tf32f(__uint_as_float(d[jg * 4 + 2]) * inv);
            o.w = tf32f(__uint_as_float(d[jg * 4 + 3]) * inv);
            const size_t oidx = ((size_t)(col >> 5) * M_TOK + row) * 32 +
                                ((((col >> 2) & 7) ^ rw7) << 2);
            *(float4*)(pool + oidx) = o;
        }
    }

    __syncthreads();
    if ((tx >> 5) == 0) TCGEN05_DEALLOC(tmem, 64);
#endif // HAS_TCGEN05
}

// ---------------- launcher ----------------
extern "C" void kernel_launch(void* const* d_in, const int* in_sizes, int n_in,
                              void* d_out, int out_size)
{
    const float* x     = (const float*)d_in[0];
    const unsigned char* mask = (const unsigned char*)d_in[1];
    const float* ln1_g = (const float*)d_in[2];
    const float* ln1_b = (const float*)d_in[3];
    const float* wq    = (const float*)d_in[4];
    const float* bq    = (const float*)d_in[5];
    const float* wk    = (const float*)d_in[6];
    const float* bk    = (const float*)d_in[7];
    const float* wv    = (const float*)d_in[8];
    const float* bv    = (const float*)d_in[9];
    const float* wo    = (const float*)d_in[10];
    const float* bo    = (const float*)d_in[11];
    const float* ln2_g = (const float*)d_in[12];
    const float* ln2_b = (const float*)d_in[13];
    const float* w1    = (const float*)d_in[14];
    const float* b1    = (const float*)d_in[15];
    const float* w2    = (const float*)d_in[16];
    const float* b2    = (const float*)d_in[17];
    float* out = (float*)d_out;

    float* scratch = nullptr;
    cudaGetSymbolAddress((void**)&scratch, g_scratch);
    float* xn    = scratch + OFF_XN;
    float* vbuf  = scratch + OFF_V;
    float* pool  = scratch + OFF_POOL;
    float* x2    = scratch + OFF_X2;
    float* hbuf  = scratch + OFF_H;
    float* qsb   = scratch + OFF_QS;
    float* ksb   = scratch + OFF_KS;
    float* wqk   = scratch + OFF_WQK;
    float* bqk   = scratch + OFF_BQK;
    float* wvt   = scratch + OFF_WVT;
    float* wot   = scratch + OFF_WOT;
    float* w1t   = scratch + OFF_W1T;
    float* w2t   = scratch + OFF_W2T;
    float4* kstat = (float4*)(scratch + OFF_KSTAT);

    cudaFuncSetAttribute(sgemm_tc<false, false, false, true >, cudaFuncAttributeMaxDynamicSharedMemorySize, TC_SMEM_TOTAL);
    cudaFuncSetAttribute(sgemm_tc<false, true,  false, false>, cudaFuncAttributeMaxDynamicSharedMemorySize, TC_SMEM_TOTAL);
    cudaFuncSetAttribute(sgemm_tc<true,  false, true,  false>, cudaFuncAttributeMaxDynamicSharedMemorySize, TC_SMEM_TOTAL);
    cudaFuncSetAttribute(attn_kernel, cudaFuncAttributeMaxDynamicSharedMemorySize, AT_SMEM_TOTAL);

    // weight transposes into chunked+rounded layout
    transpose_kernel<<<dim3(32, 32),  256>>>(wv, wvt, D_MODEL, D_MODEL);
    transpose_kernel<<<dim3(32, 32),  256>>>(wo, wot, D_MODEL, D_MODEL);
    transpose_kernel<<<dim3(128, 32), 256>>>(w1, w1t, D_MODEL, FF_DIM);
    transpose_kernel<<<dim3(32, 128), 256>>>(w2, w2t, FF_DIM, D_MODEL);

    // 1. xn = LN1(x)  (chunked, tf32-rounded)
    ln_kernel<<<M_TOK, 256>>>(x, ln1_g, ln1_b, xn);
    // 2. fold head-sums of wq/wk (rank-1 attention)
    headsum_kernel<<<64, 256>>>(wq, bq, wk, bk, wqk, bqk);
    // 3. v = xn @ wv + bv   (row-major, tf32-rounded for attention MMA)
    sgemm_tc<false, false, false, true><<<dim3(D_MODEL / 256, M_TOK / 256), 256, TC_SMEM_TOTAL>>>(
        xn, wvt, bv, nullptr, vbuf, D_MODEL, D_MODEL);
    // 4. qs/ks = xn @ wqk + bqk
    qsks_gemm<<<M_TOK / 64, 256>>>(xn, wqk, bqk, qsb, ksb);
    // 5. per-(b,h) key stats for closed-form softmax max
    kminmax_kernel<<<BATCH * NHEAD, 256>>>(ksb, mask, kstat);
    // 6. pooled = softmax(qs ⊗ ks, masked) @ v   (tensor-core, chunked out)
    attn_kernel<<<dim3(SEQ / 128, BATCH * NHEAD), 256, AT_SMEM_TOTAL>>>(
        qsb, ksb, vbuf, mask, kstat, pool);
    // 7. x2 = pooled @ wo + bo + x
    sgemm_tc<false, true, false, false><<<dim3(D_MODEL / 256, M_TOK / 256), 256, TC_SMEM_TOTAL>>>(
        pool, wot, bo, x, x2, D_MODEL, D_MODEL);
    // 8. xn = LN2(x2)
    ln_kernel<<<M_TOK, 256>>>(x2, ln2_g, ln2_b, xn);
    // 9. h = relu(xn @ w1 + b1)   (chunked+rounded out)
    sgemm_tc<true, false, true, false><<<dim3(FF_DIM / 256, M_TOK / 256), 256, TC_SMEM_TOTAL>>>(
        xn, w1t, b1, nullptr, hbuf, FF_DIM, D_MODEL);
    // 10. out = h @ w2 + b2 + x2
    sgemm_tc<false, true, false, false><<<dim3(D_MODEL / 256, M_TOK / 256), 256, TC_SMEM_TOTAL>>>(
        hbuf, w2t, b2, x2, out, D_MODEL, FF_DIM);
}

// round 9
// speedup vs baseline: 20.0793x; 1.2502x over previous
#include <cuda_runtime.h>
#include <cuda_fp16.h>
#include <cstddef>
#include <cstdint>

// Problem constants
#define M_TOK   8192     // M*B token rows
#define D_MODEL 1024
#define FF_DIM  4096
#define NHEAD   16
#define DHEAD   64
#define SEQ     1024
#define BATCH   8

// tcgen05 is arch-SPECIFIC (sm_103a). nvcc also runs a generic compute_103 PTX
// pass where these instructions don't exist — compile a stub there.
#if defined(__CUDA_ARCH__) && (defined(__CUDA_ARCH_FEAT_SM103_ALL) || defined(__CUDA_ARCH_SPECIFIC__))
#define HAS_TCGEN05 1
#else
#define HAS_TCGEN05 0
#endif

// ---------------- tcgen05 / TMA helpers ----------------
static constexpr uint64_t SMEM_DESC_BASE_SW128 =
    (uint64_t(2)  << 61) | (uint64_t(1) << 46) | (uint64_t(64) << 32) | (uint64_t(1) << 16);
#define MAKE_SMEM_DESC(base_addr) \
    (SMEM_DESC_BASE_SW128 | ((uint64_t)((base_addr) >> 4) & 0x3FFF))

__device__ __forceinline__ uint32_t smem_to_u32(const void* p) {
    uint32_t a;
    asm("{ .reg .u64 t; cvta.to.shared.u64 t, %1; cvt.u32.u64 %0, t; }" : "=r"(a) : "l"(p));
    return a;
}

#if HAS_TCGEN05
#define TCGEN05_ALLOC(smem_res, nCols) \
    asm volatile("tcgen05.alloc.cta_group::1.sync.aligned.shared::cta.b32 [%0], %1;" \
                 :: "r"((uint32_t)(smem_res)), "r"((uint32_t)(nCols)) : "memory")
#define TCGEN05_DEALLOC(tmem, nCols) \
    asm volatile("tcgen05.dealloc.cta_group::1.sync.aligned.b32 %0, %1;" \
                 :: "r"(tmem), "r"((uint32_t)(nCols)))
#define TCGEN05_RELINQUISH() \
    asm volatile("tcgen05.relinquish_alloc_permit.cta_group::1.sync.aligned;")
#define TCGEN05_WAIT_LD() asm volatile("tcgen05.wait::ld.sync.aligned;" ::: "memory")
#define TC_FENCE_AFTER()  asm volatile("tcgen05.fence::after_thread_sync;" ::: "memory")
#define TC_COMMIT(mbar) \
    asm volatile("tcgen05.commit.cta_group::1.mbarrier::arrive::one.shared::cluster.b64 [%0];" \
                 :: "r"((uint32_t)(mbar)) : "memory")
#endif

#define FENCE_PROXY_ASYNC() asm volatile("fence.proxy.async.shared::cta;" ::: "memory")
#define MBARRIER_INIT(mbar, cnt) \
    asm volatile("mbarrier.init.shared.b64 [%0], %1;" :: "r"((uint32_t)(mbar)), "r"((uint32_t)(cnt)) : "memory")
#define MBARRIER_EXPECT_TX(mbar, bytes) \
    asm volatile("mbarrier.arrive.expect_tx.shared.b64 _, [%0], %1;" \
                 :: "r"((uint32_t)(mbar)), "r"((uint32_t)(bytes)) : "memory")
#define MBAR_WAIT(mbar, ph) \
    asm volatile("{\n\t.reg .pred P;\n\tWL%=:\n\t" \
                 "mbarrier.try_wait.parity.acquire.cta.shared::cta.b64 P, [%0], %1, 0x989680;\n\t" \
                 "@!P bra WL%=;\n\t}" :: "r"((uint32_t)(mbar)), "r"((uint32_t)(ph)) : "memory")
#define BULK_G2S(dst, src, bytes, mbar) \
    asm volatile("cp.async.bulk.shared::cta.global.mbarrier::complete_tx::bytes [%0], [%1], %2, [%3];" \
                 :: "r"((uint32_t)(dst)), "l"(src), "r"((uint32_t)(bytes)), "r"((uint32_t)(mbar)) : "memory")

#if HAS_TCGEN05
#define TCGEN05_LD_32X32B_X32(r, tmem_addr) \
    asm volatile( \
        "tcgen05.ld.sync.aligned.32x32b.x32.b32 " \
        "{%0, %1, %2, %3, %4, %5, %6, %7, " \
        " %8, %9, %10, %11, %12, %13, %14, %15, " \
        " %16, %17, %18, %19, %20, %21, %22, %23, " \
        " %24, %25, %26, %27, %28, %29, %30, %31}, [%32];" \
        : "=r"((r)[0]),  "=r"((r)[1]),  "=r"((r)[2]),  "=r"((r)[3]), \
          "=r"((r)[4]),  "=r"((r)[5]),  "=r"((r)[6]),  "=r"((r)[7]), \
          "=r"((r)[8]),  "=r"((r)[9]),  "=r"((r)[10]), "=r"((r)[11]), \
          "=r"((r)[12]), "=r"((r)[13]), "=r"((r)[14]), "=r"((r)[15]), \
          "=r"((r)[16]), "=r"((r)[17]), "=r"((r)[18]), "=r"((r)[19]), \
          "=r"((r)[20]), "=r"((r)[21]), "=r"((r)[22]), "=r"((r)[23]), \
          "=r"((r)[24]), "=r"((r)[25]), "=r"((r)[26]), "=r"((r)[27]), \
          "=r"((r)[28]), "=r"((r)[29]), "=r"((r)[30]), "=r"((r)[31]) \
        : "r"(tmem_addr))

// f16 SS MMA, cg1. idesc: dtype F32(1<<4) | atype F16(0) | btype F16(0)
//                        | (N/8)<<17 | (M/16)<<24
__device__ __forceinline__ void mma_f16_ss(uint32_t d_tmem, uint64_t a_desc, uint64_t b_desc,
                                           uint32_t idesc, uint32_t en)
{
    asm volatile(
        "{\n\t"
        ".reg .pred p;\n\t"
        "setp.ne.u32 p, %5, 0;\n\t"
        "tcgen05.mma.cta_group::1.kind::f16 [%0], %1, %2, %3, {%4, %4, %4, %4}, p;\n\t"
        "}"
        :: "r"(d_tmem), "l"(a_desc), "l"(b_desc), "r"(idesc), "r"(0u), "r"(en)
        : "memory");
}
#endif

// ============ chunked + pre-swizzled fp16 GEMM operand layout =================
// element (row, k): chunk = 64 K values per 128B row, SW128 16B-block perm baked:
//   half_index = ((k>>6)*R + row)*64 + ((((k>>3)&7) ^ (row&7))<<3) + (k&7)
__device__ __forceinline__ size_t hchunk_idx(int row, int k, int R) {
    return ((size_t)(k >> 6) * R + row) * 64 + ((((k >> 3) & 7) ^ (row & 7)) << 3) + (k & 7);
}

// ---------------- scratch (static device memory; float-array backing) --------
static const size_t OFF_XN    = 0;          // half [16][8192][64]
static const size_t OFF_V     = 4194304;    // half row-major [8192][1024]
static const size_t OFF_POOL  = 8388608;    // half chunked
static const size_t OFF_X2    = 12582912;   // fp32 [8192][1024]
static const size_t OFF_H     = 20971520;   // half chunked [64][8192][64]
static const size_t OFF_QS    = 37748736;
static const size_t OFF_KS    = 37879808;
static const size_t OFF_WQK   = 38010880;   // fp32 [1024][32]
static const size_t OFF_BQK   = 38043648;
static const size_t OFF_WVT   = 38043680;   // half chunked
static const size_t OFF_WOT   = 38567968;
static const size_t OFF_W1T   = 39092256;
static const size_t OFF_W2T   = 41189408;
static const size_t OFF_KSTAT = 43286560;
static const size_t SCRATCH_FLOATS = 43287072;

__device__ float g_scratch[SCRATCH_FLOATS];

// ---------------- LayerNorm: row-major fp32 in -> chunked fp16 out ----------
__global__ void __launch_bounds__(256)
ln_kernel(const float* __restrict__ x, const float* __restrict__ g,
          const float* __restrict__ bta, __half* __restrict__ y)
{
    const int row = blockIdx.x;
    const int tx  = threadIdx.x;
    const float4 v = ((const float4*)(x + (size_t)row * D_MODEL))[tx];

    float s  = v.x + v.y + v.z + v.w;
    float sq = v.x * v.x + v.y * v.y + v.z * v.z + v.w * v.w;
    #pragma unroll
    for (int o = 16; o; o >>= 1) {
        s  += __shfl_xor_sync(0xffffffffu, s,  o);
        sq += __shfl_xor_sync(0xffffffffu, sq, o);
    }
    __shared__ float ss[8], ssq[8];
    const int w = tx >> 5, l = tx & 31;
    if (l == 0) { ss[w] = s; ssq[w] = sq; }
    __syncthreads();
    s = 0.f; sq = 0.f;
    #pragma unroll
    for (int i = 0; i < 8; i++) { s += ss[i]; sq += ssq[i]; }

    const float mean = s * (1.f / D_MODEL);
    const float var  = sq * (1.f / D_MODEL) - mean * mean;
    const float rstd = rsqrtf(var + 1e-5f);

    const float4 gv = ((const float4*)g)[tx];
    const float4 bv = ((const float4*)bta)[tx];
    const __half2 h01 = __floats2half2_rn((v.x - mean) * rstd * gv.x + bv.x,
                                          (v.y - mean) * rstd * gv.y + bv.y);
    const __half2 h23 = __floats2half2_rn((v.z - mean) * rstd * gv.z + bv.z,
                                          (v.w - mean) * rstd * gv.w + bv.w);
    // k = 4*tx
    const size_t oidx = ((size_t)(tx >> 4) * M_TOK + row) * 64 +
                        ((((tx >> 1) & 7) ^ (row & 7)) << 3) + ((tx & 1) << 2);
    __half2* dst = (__half2*)(y + oidx);
    dst[0] = h01; dst[1] = h23;
}

// ---------------- transpose into chunked fp16: in[K][N] -> outT(n,k) --------
__global__ void __launch_bounds__(256)
transpose_kernel(const float* __restrict__ in, __half* __restrict__ out, int K, int N)
{
    __shared__ float t[32][33];
    const int k0 = blockIdx.y << 5;
    const int n0 = blockIdx.x << 5;
    const int tx = threadIdx.x & 31;
    const int ty = threadIdx.x >> 5;   // 0..7
    #pragma unroll
    for (int i = 0; i < 4; i++)
        t[ty + (i << 3)][tx] = in[(size_t)(k0 + ty + (i << 3)) * N + n0 + tx];
    __syncthreads();
    #pragma unroll
    for (int i = 0; i < 4; i++) {
        const int n = n0 + ty + (i << 3);
        const int k = k0 + tx;
        out[hchunk_idx(n, k, N)] = __float2half_rn(t[tx][ty + (i << 3)]);
    }
}

// ---------------- head-sum of wq/wk columns into combined [1024][32] ---------
__global__ void headsum_kernel(const float* __restrict__ wq, const float* __restrict__ bq,
                               const float* __restrict__ wk, const float* __restrict__ bk,
                               float* __restrict__ wqk, float* __restrict__ bqk)
{
    const int idx = blockIdx.x * blockDim.x + threadIdx.x;
    if (idx < D_MODEL * NHEAD) {
        const int d = idx >> 4, h = idx & 15;
        const float* pq = wq + (size_t)d * D_MODEL + h * DHEAD;
        const float* pk = wk + (size_t)d * D_MODEL + h * DHEAD;
        float sq = 0.f, sk = 0.f;
        #pragma unroll 8
        for (int i = 0; i < DHEAD; i++) { sq += pq[i]; sk += pk[i]; }
        wqk[d * 32 + h]      = sq;
        wqk[d * 32 + 16 + h] = sk;
    }
    if (idx < NHEAD) {
        float sq = 0.f, sk = 0.f;
        for (int i = 0; i < DHEAD; i++) {
            sq += bq[idx * DHEAD + i];
            sk += bk[idx * DHEAD + i];
        }
        bqk[idx] = sq; bqk[16 + idx] = sk;
    }
}

// ---------------- skinny GEMM: C[8192,32] = xn(fp16 chunked) @ wqk + bqk -----
__global__ void __launch_bounds__(256)
qsks_gemm(const __half* __restrict__ xn, const float* __restrict__ wqk,
          const float* __restrict__ bqk, float* __restrict__ qs, float* __restrict__ ks)
{
    __shared__ __half Araw[4096];     // 64 rows x 64 halves (one 64-K chunk)
    __shared__ float Wsm[64][36];

    const int tx = threadIdx.x;
    const int r  = tx >> 2;           // 0..63
    const int cg = tx & 3;
    const int brow = blockIdx.x << 6;
    const int p7 = r & 7;

    float acc[8];
    #pragma unroll
    for (int j = 0; j < 8; j++) acc[j] = 0.f;

    for (int chk = 0; chk < 16; chk++) {
        const uint4* src = (const uint4*)(xn + ((size_t)chk * M_TOK + brow) * 64);
        ((uint4*)Araw)[tx]       = src[tx];
        ((uint4*)Araw)[tx + 256] = src[tx + 256];
        {
            const int row = tx >> 3, c4 = (tx & 7) << 2;
            *(float4*)&Wsm[row][c4]      = *(const float4*)(wqk + (size_t)(chk * 64 + row) * 32 + c4);
            *(float4*)&Wsm[row + 32][c4] = *(const float4*)(wqk + (size_t)(chk * 64 + row + 32) * 32 + c4);
        }
        __syncthreads();

        #pragma unroll
        for (int j = 0; j < 8; j++) {
            const uint4 ab = *(const uint4*)&Araw[r * 64 + ((j ^ p7) << 3)];
            const __half2* hp = (const __half2*)&ab;
            #pragma unroll
            for (int e = 0; e < 4; e++) {
                const float2 f2 = __half22float2(hp[e]);
                const int kk = j * 8 + e * 2;
                {
                    const float4 w0 = *(const float4*)&Wsm[kk][cg * 8];
                    const float4 w1 = *(const float4*)&Wsm[kk][cg * 8 + 4];
                    acc[0] = fmaf(f2.x, w0.x, acc[0]); acc[1] = fmaf(f2.x, w0.y, acc[1]);
                    acc[2] = fmaf(f2.x, w0.z, acc[2]); acc[3] = fmaf(f2.x, w0.w, acc[3]);
                    acc[4] = fmaf(f2.x, w1.x, acc[4]); acc[5] = fmaf(f2.x, w1.y, acc[5]);
                    acc[6] = fmaf(f2.x, w1.z, acc[6]); acc[7] = fmaf(f2.x, w1.w, acc[7]);
                }
                {
                    const float4 w0 = *(const float4*)&Wsm[kk + 1][cg * 8];
                    const float4 w1 = *(const float4*)&Wsm[kk + 1][cg * 8 + 4];
                    acc[0] = fmaf(f2.y, w0.x, acc[0]); acc[1] = fmaf(f2.y, w0.y, acc[1]);
                    acc[2] = fmaf(f2.y, w0.z, acc[2]); acc[3] = fmaf(f2.y, w0.w, acc[3]);
                    acc[4] = fmaf(f2.y, w1.x, acc[4]); acc[5] = fmaf(f2.y, w1.y, acc[5]);
                    acc[6] = fmaf(f2.y, w1.z, acc[6]); acc[7] = fmaf(f2.y, w1.w, acc[7]);
                }
            }
        }
        __syncthreads();
    }

    const size_t row = (size_t)(brow + r);
    #pragma unroll
    for (int j = 0; j < 8; j++) {
        const int c = cg * 8 + j;
        const float v = acc[j] + bqk[c];
        if (c < 16) qs[row * NHEAD + c]        = v;
        else        ks[row * NHEAD + (c - 16)] = v;
    }
}

// ---------------- per-(b,h) key stats: kmax/kmin over unmasked, anyMasked ----
__global__ void __launch_bounds__(256)
kminmax_kernel(const float* __restrict__ ks, const unsigned char* __restrict__ mask,
               float4* __restrict__ kstat)
{
    const int bh = blockIdx.x;
    const int b  = bh >> 4;
    const int h  = bh & 15;
    const int tx = threadIdx.x;

    float kmx = -1e30f, kmn = 1e30f;
    int cnt = 0, anym = 0;
    for (int n = tx; n < SEQ; n += 256) {
        const float kv = ks[((size_t)n * BATCH + b) * NHEAD + h];
        if (mask[(size_t)n * BATCH + b]) anym = 1;
        else { kmx = fmaxf(kmx, kv); kmn = fminf(kmn, kv); cnt++; }
    }
    __shared__ float smx[256], smn[256];
    __shared__ int scnt[256], sany[256];
    smx[tx] = kmx; smn[tx] = kmn; scnt[tx] = cnt; sany[tx] = anym;
    __syncthreads();
    for (int o = 128; o; o >>= 1) {
        if (tx < o) {
            smx[tx] = fmaxf(smx[tx], smx[tx + o]);
            smn[tx] = fminf(smn[tx], smn[tx + o]);
            scnt[tx] += scnt[tx + o];
            sany[tx] |= sany[tx + o];
        }
        __syncthreads();
    }
    if (tx == 0)
        kstat[bh] = make_float4(smx[0], smn[0], sany[0] ? 1.f : 0.f, (float)scnt[0]);
}

// ======== tcgen05 f16 GEMM: 256x256 supertile, 3-stage cp.async.bulk pipeline ========
// A chunked fp16 [K/64][M_TOK][64]; Wt chunked fp16 [K/64][N][64].
// OUTMODE: 0 = fp32 row-major, 1 = fp16 chunked, 2 = fp16 row-major.
#define TC_STAGES   3
#define TC_HDR      1024
#define TC_STAGE_SZ 65536
#define TC_SMEM_TOTAL (TC_HDR + TC_STAGES * TC_STAGE_SZ)   // 197632
#define TC_IDESC  ((1u << 4) | (32u << 17) | (8u << 24))   // f16, N=256, M=128

template<bool RELU, bool RESID, int OUTMODE>
__global__ void __launch_bounds__(256)
sgemm_tc(const __half* __restrict__ A, const __half* __restrict__ Wt,
         const float* __restrict__ bias, const float* __restrict__ resid,
         void* __restrict__ C, int N, int K)
{
#if HAS_TCGEN05
    extern __shared__ char sm[];
    const uint32_t sb = smem_to_u32(sm);
    const int tx = threadIdx.x;
    const int brow = blockIdx.y << 8;
    const int bcol = blockIdx.x << 8;

    if ((tx >> 5) == 0) TCGEN05_ALLOC(sb, 512);
    if (tx == 0) {
        #pragma unroll
        for (int s = 0; s < TC_STAGES; s++) {
            MBARRIER_INIT(sb + 8 + s * 8, 1);
            MBARRIER_INIT(sb + 32 + s * 8, 1);
        }
    }
    __syncthreads();
    if ((tx >> 5) == 0) TCGEN05_RELINQUISH();
    uint32_t tmem;
    asm volatile("ld.shared.b32 %0, [%1];" : "=r"(tmem) : "r"(sb));

    const int nchunk = K >> 6;

    if (tx == 0) {
        TC_FENCE_AFTER();
        #pragma unroll
        for (int i = 0; i < TC_STAGES; i++) {
            const int s = i;
            const uint32_t full = sb + 8 + s * 8;
            MBARRIER_EXPECT_TX(full, 2 * 32768);
            BULK_G2S(sb + TC_HDR + s * TC_STAGE_SZ,
                     A + ((size_t)i * M_TOK + brow) * 64, 32768, full);
            BULK_G2S(sb + TC_HDR + s * TC_STAGE_SZ + 32768,
                     Wt + ((size_t)i * N + bcol) * 64, 32768, full);
        }
        for (int i = 0; i < nchunk; i++) {
            const int s = i % TC_STAGES;
            const int ph = (i / TC_STAGES) & 1;
            MBAR_WAIT(sb + 8 + s * 8, ph);
            const uint32_t abase = sb + TC_HDR + s * TC_STAGE_SZ;
            const uint64_t ad0 = MAKE_SMEM_DESC(abase);
            const uint64_t ad1 = MAKE_SMEM_DESC(abase + 16384);
            const uint64_t bd  = MAKE_SMEM_DESC(abase + 32768);
            #pragma unroll
            for (int k8 = 0; k8 < 4; k8++) {
                const uint32_t en = (i | k8) ? 1u : 0u;
                mma_f16_ss(tmem,       ad0 + 2 * k8, bd + 2 * k8, TC_IDESC, en);
                mma_f16_ss(tmem + 256, ad1 + 2 * k8, bd + 2 * k8, TC_IDESC, en);
            }
            TC_COMMIT(sb + 32 + s * 8);
            const int j = i + TC_STAGES;
            if (j < nchunk) {
                MBAR_WAIT(sb + 32 + s * 8, ph);
                const uint32_t full = sb + 8 + s * 8;
                MBARRIER_EXPECT_TX(full, 2 * 32768);
                BULK_G2S(abase,         A + ((size_t)j * M_TOK + brow) * 64, 32768, full);
                BULK_G2S(abase + 32768, Wt + ((size_t)j * N + bcol) * 64, 32768, full);
            }
        }
        for (int j = nchunk - TC_STAGES; j < nchunk; j++) {
            const int s = j % TC_STAGES;
            MBAR_WAIT(sb + 32 + s * 8, (j / TC_STAGES) & 1);
        }
    }
    __syncthreads();
    TC_FENCE_AFTER();

    {
        const int w     = tx >> 5;
        const int lane  = tx & 31;
        const int mtile = w >> 2;
        const int row   = brow + (mtile << 7) + ((w & 3) << 5) + lane;
        const int rw7   = row & 7;
        #pragma unroll
        for (int slab = 0; slab < 4; slab++) {
            uint32_t d[64];
            TCGEN05_LD_32X32B_X32(d,      tmem + mtile * 256 + slab * 64);
            TCGEN05_LD_32X32B_X32(d + 32, tmem + mtile * 256 + slab * 64 + 32);
            TCGEN05_WAIT_LD();
            const int cb = bcol + slab * 64;
            const float* bp = bias + cb;
            const float* rp = RESID ? (resid + (size_t)row * N + cb) : nullptr;
            #pragma unroll
            for (int j = 0; j < 64; j += 4) {
                const float4 bv = *(const float4*)(bp + j);
                float4 o;
                o.x = __uint_as_float(d[j + 0]) + bv.x;
                o.y = __uint_as_float(d[j + 1]) + bv.y;
                o.z = __uint_as_float(d[j + 2]) + bv.z;
                o.w = __uint_as_float(d[j + 3]) + bv.w;
                if (RESID) {
                    const float4 rv = *(const float4*)(rp + j);
                    o.x += rv.x; o.y += rv.y; o.z += rv.z; o.w += rv.w;
                }
                if (RELU) {
                    o.x = fmaxf(o.x, 0.f); o.y = fmaxf(o.y, 0.f);
                    o.z = fmaxf(o.z, 0.f); o.w = fmaxf(o.w, 0.f);
                }
                if (OUTMODE == 1) {
                    const int col = cb + j;
                    const __half2 h01 = __floats2half2_rn(o.x, o.y);
                    const __half2 h23 = __floats2half2_rn(o.z, o.w);
                    const size_t oidx = ((size_t)(col >> 6) * M_TOK + row) * 64 +
                                        ((((col >> 3) & 7) ^ rw7) << 3) + (col & 7);
                    __half2* dst = (__half2*)((__half*)C + oidx);
                    dst[0] = h01; dst[1] = h23;
                } else if (OUTMODE == 2) {
                    const __half2 h01 = __floats2half2_rn(o.x, o.y);
                    const __half2 h23 = __floats2half2_rn(o.z, o.w);
                    __half2* dst = (__half2*)((__half*)C + (size_t)row * N + cb + j);
                    dst[0] = h01; dst[1] = h23;
                } else {
                    *(float4*)((float*)C + (size_t)row * N + cb + j) = o;
                }
            }
        }
    }

    __syncthreads();
    if ((tx >> 5) == 0) TCGEN05_DEALLOC(tmem, 512);
#endif // HAS_TCGEN05
}

// ================= tensor-core attention (fp16 operands) ======================
// Rank-1 scores, closed-form softmax max, TMEM accumulation over 16 key tiles.
// smem: 0 tmemptr | 8,16 done mbars | 64 lsum[256] | 1088 ksm[64] | 1344 mbits
//       | 2048 P0(16KB) | 18432 P1 | 34816 V0(8KB) | 43008 V1   => 51200 total
#define AT_SMEM_TOTAL 51200
#define AT_P(s)   (2048 + (s) * 16384)
#define AT_V(s)   (34816 + (s) * 8192)
#define AT_IDESC  ((1u << 4) | (8u << 17) | (8u << 24))   // f16, N=64, M=128

__global__ void __launch_bounds__(256)
attn_kernel(const float* __restrict__ qs, const float* __restrict__ ks,
            const __half* __restrict__ v, const unsigned char* __restrict__ mask,
            const float4* __restrict__ kstat, __half* __restrict__ pool)
{
#if HAS_TCGEN05
    extern __shared__ char sm[];
    const uint32_t sb = smem_to_u32(sm);
    float* lsum = (float*)(sm + 64);
    float* ksm  = (float*)(sm + 1088);
    unsigned* mbits = (unsigned*)(sm + 1344);

    const int tx = threadIdx.x;
    const int bh = blockIdx.y;
    const int b  = bh >> 4;
    const int h  = bh & 15;
    const int m0 = blockIdx.x << 7;

    const int q     = tx & 127;
    const int nhalf = tx >> 7;
    const int q7    = q & 7;

    if ((tx >> 5) == 0) TCGEN05_ALLOC(sb, 64);
    if (tx == 0) { MBARRIER_INIT(sb + 8, 1); MBARRIER_INIT(sb + 16, 1); }
    __syncthreads();
    if ((tx >> 5) == 0) TCGEN05_RELINQUISH();
    uint32_t tmem;
    asm volatile("ld.shared.b32 %0, [%1];" : "=r"(tmem) : "r"(sb));

    const float qv = qs[((size_t)(m0 + q) * BATCH + b) * NHEAD + h];
    const float4 kst = kstat[bh];
    float mu = (kst.w > 0.f) ? fmaxf(qv * kst.x, qv * kst.y) : -1e30f;
    const float mq = (kst.z > 0.f) ? fmaxf(mu, -1000.0f) : mu;

    float lpart = 0.f;
    int dph0 = 0, dph1 = 0;

    const int vn = tx >> 2;             // 0..63
    const int dq = (tx & 3) << 4;       // 0,16,32,48

    for (int i = 0; i < 16; i++) {
        const int s  = i & 1;
        const int n0 = i << 6;
        if (i >= 2) {
            if (s == 0) { MBAR_WAIT(sb + 8,  dph0); dph0 ^= 1; }
            else        { MBAR_WAIT(sb + 16, dph1); dph1 ^= 1; }
        }

        if (tx < 64) {
            ksm[tx] = ks[((size_t)(n0 + tx) * BATCH + b) * NHEAD + h];
            const bool mm = mask[(size_t)(n0 + tx) * BATCH + b] != 0;
            const unsigned bal = __ballot_sync(0xffffffffu, mm);
            if ((tx & 31) == 0) mbits[tx >> 5] = bal;
        }

        // V tile transpose: load 16 halves of row (n0+vn), scatter to Vt[d][n]
        {
            const __half* vp = v + ((size_t)(n0 + vn) * BATCH + b) * D_MODEL + h * DHEAD + dq;
            const uint4 va = *(const uint4*)vp;
            const uint4 vb_ = *(const uint4*)(vp + 8);
            const __half* h0 = (const __half*)&va;
            const __half* h1 = (const __half*)&vb_;
            char* vtb = sm + AT_V(s);
            const int nblk = vn >> 3;
            const int nrem = (vn & 7) << 1;
            #pragma unroll
            for (int e = 0; e < 8; e++) {
                const int d = dq + e;
                *(__half*)(vtb + d * 128 + ((nblk ^ (d & 7)) << 4) + nrem) = h0[e];
            }
            #pragma unroll
            for (int e = 0; e < 8; e++) {
                const int d = dq + 8 + e;
                *(__half*)(vtb + d * 128 + ((nblk ^ (d & 7)) << 4) + nrem) = h1[e];
            }
        }
        __syncthreads();

        // P compute: 32 exps per thread -> fp16 swizzled STS
        {
            const unsigned mb = mbits[nhalf];
            char* pb = sm + AT_P(s) + q * 128;
            #pragma unroll
            for (int g = 0; g < 4; g++) {
                __half ph[8];
                #pragma unroll
                for (int e = 0; e < 8; e++) {
                    const int np_ = g * 8 + e;
                    const float kv = ksm[nhalf * 32 + np_];
                    const float sc = ((mb >> np_) & 1u) ? -1000.0f : qv * kv;
                    ph[e] = __float2half_rn(__expf(sc - mq));
                    lpart += __half2float(ph[e]);
                }
                *(uint4*)(pb + (((nhalf * 4 + g) ^ q7) << 4)) = *(const uint4*)ph;
            }
        }
        FENCE_PROXY_ASYNC();
        __syncthreads();

        if (tx == 0) {
            TC_FENCE_AFTER();
            const uint64_t pd = MAKE_SMEM_DESC(sb + AT_P(s));
            const uint64_t vd = MAKE_SMEM_DESC(sb + AT_V(s));
            #pragma unroll
            for (int k8 = 0; k8 < 4; k8++)
                mma_f16_ss(tmem, pd + 2 * k8, vd + 2 * k8, AT_IDESC, (i | k8) ? 1u : 0u);
            TC_COMMIT(sb + 8 + s * 8);
        }
    }

    MBAR_WAIT(sb + 8,  dph0);
    MBAR_WAIT(sb + 16, dph1);
    lsum[tx] = lpart;
    __syncthreads();
    TC_FENCE_AFTER();

    const int w = tx >> 5;
    if (w < 4) {
        const int lane = tx & 31;
        const int ql   = w * 32 + lane;
        uint32_t d[64];
        TCGEN05_LD_32X32B_X32(d,      tmem);
        TCGEN05_LD_32X32B_X32(d + 32, tmem + 32);
        TCGEN05_WAIT_LD();

        const float inv = 1.f / (lsum[ql] + lsum[ql + 128]);
        const int row = (m0 + ql) * BATCH + b;
        const int rw7 = row & 7;
        #pragma unroll
        for (int jg = 0; jg < 16; jg++) {
            const int col = h * 64 + jg * 4;
            const __half2 h01 = __floats2half2_rn(__uint_as_float(d[jg * 4 + 0]) * inv,
                                                  __uint_as_float(d[jg * 4 + 1]) * inv);
            const __half2 h23 = __floats2half2_rn(__uint_as_float(d[jg * 4 + 2]) * inv,
                                                  __uint_as_float(d[jg * 4 + 3]) * inv);
            const size_t oidx = ((size_t)(col >> 6) * M_TOK + row) * 64 +
                                ((((col >> 3) & 7) ^ rw7) << 3) + (col & 7);
            __half2* dst = (__half2*)(pool + oidx);
            dst[0] = h01; dst[1] = h23;
        }
    }

    __syncthreads();
    if ((tx >> 5) == 0) TCGEN05_DEALLOC(tmem, 64);
#endif // HAS_TCGEN05
}

// ---------------- launcher ----------------
extern "C" void kernel_launch(void* const* d_in, const int* in_sizes, int n_in,
                              void* d_out, int out_size)
{
    const float* x     = (const float*)d_in[0];
    const unsigned char* mask = (const unsigned char*)d_in[1];
    const float* ln1_g = (const float*)d_in[2];
    const float* ln1_b = (const float*)d_in[3];
    const float* wq    = (const float*)d_in[4];
    const float* bq    = (const float*)d_in[5];
    const float* wk    = (const float*)d_in[6];
    const float* bk    = (const float*)d_in[7];
    const float* wv    = (const float*)d_in[8];
    const float* bv    = (const float*)d_in[9];
    const float* wo    = (const float*)d_in[10];
    const float* bo    = (const float*)d_in[11];
    const float* ln2_g = (const float*)d_in[12];
    const float* ln2_b = (const float*)d_in[13];
    const float* w1    = (const float*)d_in[14];
    const float* b1    = (const float*)d_in[15];
    const float* w2    = (const float*)d_in[16];
    const float* b2    = (const float*)d_in[17];
    float* out = (float*)d_out;

    float* scratch = nullptr;
    cudaGetSymbolAddress((void**)&scratch, g_scratch);
    __half* xn   = (__half*)(scratch + OFF_XN);
    __half* vbuf = (__half*)(scratch + OFF_V);
    __half* pool = (__half*)(scratch + OFF_POOL);
    float*  x2   = scratch + OFF_X2;
    __half* hbuf = (__half*)(scratch + OFF_H);
    float*  qsb  = scratch + OFF_QS;
    float*  ksb  = scratch + OFF_KS;
    float*  wqk  = scratch + OFF_WQK;
    float*  bqk  = scratch + OFF_BQK;
    __half* wvt  = (__half*)(scratch + OFF_WVT);
    __half* wot  = (__half*)(scratch + OFF_WOT);
    __half* w1t  = (__half*)(scratch + OFF_W1T);
    __half* w2t  = (__half*)(scratch + OFF_W2T);
    float4* kstat = (float4*)(scratch + OFF_KSTAT);

    cudaFuncSetAttribute(sgemm_tc<false, false, 2>, cudaFuncAttributeMaxDynamicSharedMemorySize, TC_SMEM_TOTAL);
    cudaFuncSetAttribute(sgemm_tc<false, true,  0>, cudaFuncAttributeMaxDynamicSharedMemorySize, TC_SMEM_TOTAL);
    cudaFuncSetAttribute(sgemm_tc<true,  false, 1>, cudaFuncAttributeMaxDynamicSharedMemorySize, TC_SMEM_TOTAL);
    cudaFuncSetAttribute(attn_kernel, cudaFuncAttributeMaxDynamicSharedMemorySize, AT_SMEM_TOTAL);

    // weight transposes into chunked fp16 layout
    transpose_kernel<<<dim3(32, 32),  256>>>(wv, wvt, D_MODEL, D_MODEL);
    transpose_kernel<<<dim3(32, 32),  256>>>(wo, wot, D_MODEL, D_MODEL);
    transpose_kernel<<<dim3(128, 32), 256>>>(w1, w1t, D_MODEL, FF_DIM);
    transpose_kernel<<<dim3(32, 128), 256>>>(w2, w2t, FF_DIM, D_MODEL);

    // 1. xn = LN1(x)  (chunked fp16)
    ln_kernel<<<M_TOK, 256>>>(x, ln1_g, ln1_b, xn);
    // 2. fold head-sums of wq/wk
    headsum_kernel<<<64, 256>>>(wq, bq, wk, bk, wqk, bqk);
    // 3. v = xn @ wv + bv   (fp16 row-major out)
    sgemm_tc<false, false, 2><<<dim3(D_MODEL / 256, M_TOK / 256), 256, TC_SMEM_TOTAL>>>(
        xn, wvt, bv, nullptr, vbuf, D_MODEL, D_MODEL);
    // 4. qs/ks = xn @ wqk + bqk
    qsks_gemm<<<M_TOK / 64, 256>>>(xn, wqk, bqk, qsb, ksb);
    // 5. key stats for closed-form softmax max
    kminmax_kernel<<<BATCH * NHEAD, 256>>>(ksb, mask, kstat);
    // 6. pooled = softmax(qs ⊗ ks, masked) @ v   (chunked fp16 out)
    attn_kernel<<<dim3(SEQ / 128, BATCH * NHEAD), 256, AT_SMEM_TOTAL>>>(
        qsb, ksb, vbuf, mask, kstat, pool);
    // 7. x2 = pooled @ wo + bo + x   (fp32 row out)
    sgemm_tc<false, true, 0><<<dim3(D_MODEL / 256, M_TOK / 256), 256, TC_SMEM_TOTAL>>>(
        pool, wot, bo, x, x2, D_MODEL, D_MODEL);
    // 8. xn = LN2(x2)
    ln_kernel<<<M_TOK, 256>>>(x2, ln2_g, ln2_b, xn);
    // 9. h = relu(xn @ w1 + b1)   (chunked fp16 out)
    sgemm_tc<true, false, 1><<<dim3(FF_DIM / 256, M_TOK / 256), 256, TC_SMEM_TOTAL>>>(
        xn, w1t, b1, nullptr, hbuf, FF_DIM, D_MODEL);
    // 10. out = h @ w2 + b2 + x2
    sgemm_tc<false, true, 0><<<dim3(D_MODEL / 256, M_TOK / 256), 256, TC_SMEM_TOTAL>>>(
        hbuf, w2t, b2, x2, out, D_MODEL, FF_DIM);
}